// round 1
// baseline (speedup 1.0000x reference)
#include <cuda_runtime.h>
#include <math.h>

#define N_NODES 50000
#define N_EDGES 200000
#define IN_CH   256
#define HID     768
#define OUTD    768
#define N_REL   5
#define N_BASES 4
#define NCAT    (6*768)   /* [root | w0..w4] = 4608 columns */

// ---------------- static device scratch (no allocations allowed) -------------
__device__ float g_H[(size_t)N_NODES * NCAT];     // 921.6 MB GEMM output
__device__ float g_acc[(size_t)N_NODES * HID];    // layer-1 accumulator / layer-2 input
__device__ float g_W[(size_t)HID * NCAT];         // concatenated weights (max K=768)
__device__ int   g_cnt[N_NODES * N_REL];
__device__ int   g_esrc[N_EDGES];
__device__ int   g_edst[N_EDGES];
__device__ int   g_etyp[N_EDGES];
__device__ float g_escl[N_EDGES];
__device__ int   g_is64;

// ---------------- index-width detection (int32 vs int64 dump) ----------------
__global__ void k_detect(const int* ei) {
    __shared__ int found;
    if (threadIdx.x == 0) found = 0;
    __syncthreads();
    // If data is int64 (values < 2^31), every odd 32-bit word is 0.
    // If int32, odd words are random node ids in [0,50000): ~never all zero.
    for (int i = threadIdx.x; i < 2048; i += blockDim.x)
        if (ei[2 * i + 1] != 0) found = 1;
    __syncthreads();
    if (threadIdx.x == 0) g_is64 = (found == 0) ? 1 : 0;
}

__device__ __forceinline__ int idx_at(const void* p, long long i, int is64) {
    return is64 ? (int)((const long long*)p)[i] : ((const int*)p)[i];
}

// ---------------- edge preprocessing ----------------
__global__ void k_zero_cnt() {
    int i = blockIdx.x * blockDim.x + threadIdx.x;
    if (i < N_NODES * N_REL) g_cnt[i] = 0;
}

__global__ void k_prep(const void* ei, const void* et) {
    int e = blockIdx.x * blockDim.x + threadIdx.x;
    if (e >= N_EDGES) return;
    int is64 = g_is64;
    int s = idx_at(ei, e, is64);
    int d = idx_at(ei, (long long)N_EDGES + e, is64);
    int t = idx_at(et, e, is64);
    g_esrc[e] = s; g_edst[e] = d; g_etyp[e] = t;
    atomicAdd(&g_cnt[d * N_REL + t], 1);
}

__global__ void k_scale() {
    int e = blockIdx.x * blockDim.x + threadIdx.x;
    if (e >= N_EDGES) return;
    int c = g_cnt[g_edst[e] * N_REL + g_etyp[e]];
    g_escl[e] = 1.0f / (float)max(c, 1);
}

// ---------------- weight concatenation: g_W[K, 4608] ----------------
__global__ void k_buildW(const float* __restrict__ root,
                         const float* __restrict__ basis,
                         const float* __restrict__ comp, int K) {
    long long i = (long long)blockIdx.x * blockDim.x + threadIdx.x;
    long long tot = (long long)K * NCAT;
    if (i >= tot) return;
    int k = (int)(i / NCAT), c = (int)(i % NCAT);
    float v;
    if (c < 768) {
        v = root[(long long)k * 768 + c];
    } else {
        int r = c / 768 - 1, f = c % 768;
        v = 0.0f;
        #pragma unroll
        for (int b = 0; b < N_BASES; b++)
            v += comp[r * N_BASES + b] * basis[((long long)b * K + k) * 768 + f];
    }
    g_W[i] = v;
}

// ---------------- SGEMM: C[M,4608] = A[M,K] @ g_W[K,4608] ----------------
#define BM 128
#define BN 128
#define BK 16
#define TM 8
#define TN 8

__global__ __launch_bounds__(256, 2)
void k_sgemm(const float* __restrict__ A, float* __restrict__ C, int M, int K) {
    const int N = NCAT;
    __shared__ float As[BK][BM + 4];
    __shared__ float Bs[BK][BN];
    int tid  = threadIdx.x;
    int row0 = blockIdx.y * BM;
    int col0 = blockIdx.x * BN;
    int tx = (tid % 16) * TN;
    int ty = (tid / 16) * TM;

    float acc[TM][TN] = {};

    for (int k0 = 0; k0 < K; k0 += BK) {
        #pragma unroll
        for (int i = 0; i < 2; i++) {
            int t = tid + i * 256;
            int ar = t >> 2, ac = (t & 3) * 4;
            float4 v = make_float4(0.f, 0.f, 0.f, 0.f);
            int gr = row0 + ar;
            if (gr < M) v = *(const float4*)&A[(long long)gr * K + k0 + ac];
            As[ac + 0][ar] = v.x; As[ac + 1][ar] = v.y;
            As[ac + 2][ar] = v.z; As[ac + 3][ar] = v.w;
        }
        #pragma unroll
        for (int i = 0; i < 2; i++) {
            int t = tid + i * 256;
            int br = t >> 5, bc = (t & 31) * 4;
            *(float4*)&Bs[br][bc] =
                *(const float4*)&g_W[(long long)(k0 + br) * N + col0 + bc];
        }
        __syncthreads();

        #pragma unroll
        for (int kk = 0; kk < BK; kk++) {
            float a[TM], b[TN];
            float4 a0 = *(const float4*)&As[kk][ty];
            float4 a1 = *(const float4*)&As[kk][ty + 4];
            a[0]=a0.x; a[1]=a0.y; a[2]=a0.z; a[3]=a0.w;
            a[4]=a1.x; a[5]=a1.y; a[6]=a1.z; a[7]=a1.w;
            float4 b0 = *(const float4*)&Bs[kk][tx];
            float4 b1 = *(const float4*)&Bs[kk][tx + 4];
            b[0]=b0.x; b[1]=b0.y; b[2]=b0.z; b[3]=b0.w;
            b[4]=b1.x; b[5]=b1.y; b[6]=b1.z; b[7]=b1.w;
            #pragma unroll
            for (int i = 0; i < TM; i++)
                #pragma unroll
                for (int j = 0; j < TN; j++)
                    acc[i][j] = fmaf(a[i], b[j], acc[i][j]);
        }
        __syncthreads();
    }

    #pragma unroll
    for (int i = 0; i < TM; i++) {
        int gr = row0 + ty + i;
        if (gr >= M) continue;
        #pragma unroll
        for (int j = 0; j < TN; j += 4) {
            *(float4*)&C[(long long)gr * N + col0 + tx + j] =
                make_float4(acc[i][j], acc[i][j+1], acc[i][j+2], acc[i][j+3]);
        }
    }
}

// ---------------- aggregation / pointwise ----------------
// out[n,f] = H[n,f] + bias[f]   (root part + bias)
__global__ void k_init(float* __restrict__ out, const float* __restrict__ bias) {
    long long i = (long long)blockIdx.x * blockDim.x + threadIdx.x;
    if (i >= (long long)N_NODES * 192) return;
    int f4 = (int)(i % 192);
    long long n = i / 192;
    float4 h = *(const float4*)&g_H[n * NCAT + f4 * 4];
    float4 b = *(const float4*)&bias[f4 * 4];
    h.x += b.x; h.y += b.y; h.z += b.z; h.w += b.w;
    *(float4*)&out[n * 768 + f4 * 4] = h;
}

// one block per edge, 192 threads: out[dst] += H[src, (1+type)*768 + :] * scale
__global__ void k_scatter(float* __restrict__ out) {
    int e = blockIdx.x;
    int s = g_esrc[e], d = g_edst[e], t = g_etyp[e];
    float scl = g_escl[e];
    float4 v = *(const float4*)&g_H[(long long)s * NCAT + (long long)(1 + t) * 768
                                    + threadIdx.x * 4];
    float* o = &out[(long long)d * 768 + threadIdx.x * 4];
    atomicAdd(o + 0, v.x * scl);
    atomicAdd(o + 1, v.y * scl);
    atomicAdd(o + 2, v.z * scl);
    atomicAdd(o + 3, v.w * scl);
}

// in-place BN(eval) + ReLU on g_acc
__global__ void k_bnrelu(const float* __restrict__ gamma, const float* __restrict__ beta,
                         const float* __restrict__ mean,  const float* __restrict__ var) {
    long long i = (long long)blockIdx.x * blockDim.x + threadIdx.x;
    if (i >= (long long)N_NODES * 192) return;
    int f = (int)(i % 192) * 4;
    float4 v = ((float4*)g_acc)[i];
    float4 r;
    r.x = fmaxf((v.x - mean[f+0]) * rsqrtf(var[f+0] + 1e-5f) * gamma[f+0] + beta[f+0], 0.f);
    r.y = fmaxf((v.y - mean[f+1]) * rsqrtf(var[f+1] + 1e-5f) * gamma[f+1] + beta[f+1], 0.f);
    r.z = fmaxf((v.z - mean[f+2]) * rsqrtf(var[f+2] + 1e-5f) * gamma[f+2] + beta[f+2], 0.f);
    r.w = fmaxf((v.w - mean[f+3]) * rsqrtf(var[f+3] + 1e-5f) * gamma[f+3] + beta[f+3], 0.f);
    ((float4*)g_acc)[i] = r;
}

// in-place row L2 normalize, one block (192 threads) per node
__global__ void k_l2norm(float* __restrict__ out) {
    int n = blockIdx.x;
    float4 v = *(float4*)&out[(long long)n * 768 + threadIdx.x * 4];
    float ss = v.x*v.x + v.y*v.y + v.z*v.z + v.w*v.w;
    #pragma unroll
    for (int o = 16; o > 0; o >>= 1)
        ss += __shfl_xor_sync(0xffffffffu, ss, o);
    __shared__ float sw[6];
    __shared__ float s_inv;
    int wid = threadIdx.x / 32;
    if ((threadIdx.x & 31) == 0) sw[wid] = ss;
    __syncthreads();
    if (threadIdx.x == 0) {
        float tot = sw[0] + sw[1] + sw[2] + sw[3] + sw[4] + sw[5];
        s_inv = 1.0f / fmaxf(sqrtf(tot), 1e-12f);
    }
    __syncthreads();
    float inv = s_inv;
    v.x *= inv; v.y *= inv; v.z *= inv; v.w *= inv;
    *(float4*)&out[(long long)n * 768 + threadIdx.x * 4] = v;
}

// ---------------- launch ----------------
extern "C" void kernel_launch(void* const* d_in, const int* in_sizes, int n_in,
                              void* d_out, int out_size) {
    const float* x       = (const float*)d_in[0];
    const void*  ei      = d_in[1];
    const void*  et      = d_in[2];
    const float* basis1  = (const float*)d_in[3];
    const float* comp1   = (const float*)d_in[4];
    const float* root1   = (const float*)d_in[5];
    const float* bias1   = (const float*)d_in[6];
    const float* bn_g    = (const float*)d_in[7];
    const float* bn_b    = (const float*)d_in[8];
    const float* bn_m    = (const float*)d_in[9];
    const float* bn_v    = (const float*)d_in[10];
    const float* basis2  = (const float*)d_in[11];
    const float* comp2   = (const float*)d_in[12];
    const float* root2   = (const float*)d_in[13];
    const float* bias2   = (const float*)d_in[14];
    float* out = (float*)d_out;

    float* g_H_p;   cudaGetSymbolAddress((void**)&g_H_p,   g_H);
    float* g_acc_p; cudaGetSymbolAddress((void**)&g_acc_p, g_acc);

    const int EB = (N_EDGES + 255) / 256;
    const int PW = (int)(((long long)N_NODES * 192 + 255) / 256);
    dim3 gemm_grid(NCAT / BN, (N_NODES + BM - 1) / BM);

    // edge preprocessing (shared by both layers)
    k_detect<<<1, 256>>>((const int*)ei);
    k_zero_cnt<<<(N_NODES * N_REL + 255) / 256, 256>>>();
    k_prep<<<EB, 256>>>(ei, et);
    k_scale<<<EB, 256>>>();

    // ---- layer 1 ----
    k_buildW<<<(IN_CH * NCAT + 255) / 256, 256>>>(root1, basis1, comp1, IN_CH);
    k_sgemm<<<gemm_grid, 256>>>(x, g_H_p, N_NODES, IN_CH);
    k_init<<<PW, 256>>>(g_acc_p, bias1);
    k_scatter<<<N_EDGES, 192>>>(g_acc_p);
    k_bnrelu<<<PW, 256>>>(bn_g, bn_b, bn_m, bn_v);

    // ---- layer 2 ----
    k_buildW<<<(HID * NCAT + 255) / 256, 256>>>(root2, basis2, comp2, HID);
    k_sgemm<<<gemm_grid, 256>>>(g_acc_p, g_H_p, N_NODES, HID);
    k_init<<<PW, 256>>>(out, bias2);
    k_scatter<<<N_EDGES, 192>>>(out);
    k_l2norm<<<N_NODES, 192>>>(out);
}

// round 3
// speedup vs baseline: 2.0032x; 2.0032x over previous
#include <cuda_runtime.h>
#include <cstdint>
#include <math.h>

#define N_NODES 50000
#define N_EDGES 200000
#define IN_CH   256
#define HID     768
#define N_REL   5
#define N_BASES 4
#define NCAT    (6*768)   /* [root | w0..w4] = 4608 columns */

// ---------------- static device scratch (no allocations allowed) -------------
__device__ float g_H[(size_t)N_NODES * NCAT];     // GEMM output (921.6 MB)
__device__ float g_acc[(size_t)N_NODES * HID];    // layer-1 out / layer-2 in
__device__ float g_Wt[(size_t)NCAT * HID];        // W transposed: [4608, K] K-major, tf32-rounded
__device__ int   g_cnt[N_NODES * N_REL];
__device__ int   g_esrc[N_EDGES];
__device__ int   g_edst[N_EDGES];
__device__ int   g_etyp[N_EDGES];
__device__ float g_escl[N_EDGES];
__device__ int   g_is64;

// ============================ helpers ====================================
__device__ __forceinline__ float to_tf32(float x) {
    float r;
    asm("cvt.rna.tf32.f32 %0, %1;" : "=f"(r) : "f"(x));
    return r;
}
__device__ __forceinline__ void cp16(uint32_t dst, const void* src, int sz) {
    asm volatile("cp.async.cg.shared.global [%0], [%1], 16, %2;"
                 :: "r"(dst), "l"(src), "r"(sz));
}
__device__ __forceinline__ uint32_t smem_u32(const void* p) {
    uint32_t a;
    asm("{ .reg .u64 t; cvta.to.shared.u64 t, %1; cvt.u32.u64 %0, t; }"
        : "=r"(a) : "l"(p));
    return a;
}
__device__ __forceinline__ void mma16n8k8(float* d, const uint32_t* a, const uint32_t* b) {
    asm volatile(
        "mma.sync.aligned.m16n8k8.row.col.f32.tf32.tf32.f32 "
        "{%0,%1,%2,%3}, {%4,%5,%6,%7}, {%8,%9}, {%0,%1,%2,%3};"
        : "+f"(d[0]), "+f"(d[1]), "+f"(d[2]), "+f"(d[3])
        : "r"(a[0]), "r"(a[1]), "r"(a[2]), "r"(a[3]), "r"(b[0]), "r"(b[1]));
}

// ====================== tf32 mma.sync GEMM ====================================
// C[M, 4608] = A[M, K] @ g_Wt^T   (g_Wt is [4608, K] K-major)
#define BM 128
#define BN 128
#define BK 32
#define AST 36                         /* padded row stride in floats */
#define SM_BUF (BM * AST)              /* floats per A (or B) buffer  */
#define SM_TOTAL (4 * SM_BUF * 4)      /* 2 bufs x (A+B) x 4 bytes = 73728 */

__global__ void __launch_bounds__(256)
k_gemm_mma(const float* __restrict__ A, float* __restrict__ C, int M, int K) {
    extern __shared__ float sm[];
    float* As[2] = { sm,            sm + SM_BUF };
    float* Bs[2] = { sm + 2*SM_BUF, sm + 3*SM_BUF };

    const int tid  = threadIdx.x;
    const int lane = tid & 31;
    const int warp = tid >> 5;
    const int wm   = (warp & 1) * 64;   // warp offset along M
    const int wn   = (warp >> 1) * 32;  // warp offset along N
    const int row0 = blockIdx.y * BM;
    const int col0 = blockIdx.x * BN;
    const int NIT  = K / BK;

    const int g = lane >> 2;            // fragment row group
    const int c = lane & 3;             // fragment k index

    float acc[4][4][4];
    #pragma unroll
    for (int i = 0; i < 4; i++)
        #pragma unroll
        for (int j = 0; j < 4; j++)
            #pragma unroll
            for (int v = 0; v < 4; v++) acc[i][j][v] = 0.f;

    // per-thread load coordinates (4 chunks each for A and B)
    const int lr = tid >> 3;            // row within tile for chunk 0 (0..31)
    const int lc = (tid & 7) * 4;       // k-offset of 16B chunk

    auto load_buf = [&](int it) {
        const int b  = it & 1;
        const int k0 = it * BK;
        const uint32_t sA = smem_u32(As[b]);
        const uint32_t sB = smem_u32(Bs[b]);
        #pragma unroll
        for (int i = 0; i < 4; i++) {
            int r = lr + i * 32;
            int grow = row0 + r;
            const float* src = A + (long long)(grow < M ? grow : M - 1) * K + k0 + lc;
            cp16(sA + (r * AST + lc) * 4, src, (grow < M) ? 16 : 0);
        }
        #pragma unroll
        for (int i = 0; i < 4; i++) {
            int r = lr + i * 32;
            const float* src = g_Wt + (long long)(col0 + r) * K + k0 + lc;
            cp16(sB + (r * AST + lc) * 4, src, 16);
        }
        asm volatile("cp.async.commit_group;" ::: "memory");
    };

    load_buf(0);

    for (int it = 0; it < NIT; it++) {
        if (it + 1 < NIT) load_buf(it + 1);
        if (it + 1 < NIT)
            asm volatile("cp.async.wait_group 1;" ::: "memory");
        else
            asm volatile("cp.async.wait_group 0;" ::: "memory");
        __syncthreads();

        const int b = it & 1;
        const float* pa = As[b];
        const float* pb = Bs[b];

        #pragma unroll
        for (int ks = 0; ks < BK / 8; ks++) {
            const int kk = ks * 8;
            uint32_t af[4][4], bf[4][2];
            #pragma unroll
            for (int mt = 0; mt < 4; mt++) {
                int r = wm + mt * 16 + g;
                af[mt][0] = __float_as_uint(to_tf32(pa[ r      * AST + kk + c    ]));
                af[mt][1] = __float_as_uint(to_tf32(pa[(r + 8) * AST + kk + c    ]));
                af[mt][2] = __float_as_uint(to_tf32(pa[ r      * AST + kk + c + 4]));
                af[mt][3] = __float_as_uint(to_tf32(pa[(r + 8) * AST + kk + c + 4]));
            }
            #pragma unroll
            for (int nt = 0; nt < 4; nt++) {
                int n = wn + nt * 8 + g;
                bf[nt][0] = __float_as_uint(pb[n * AST + kk + c    ]);
                bf[nt][1] = __float_as_uint(pb[n * AST + kk + c + 4]);
            }
            #pragma unroll
            for (int mt = 0; mt < 4; mt++)
                #pragma unroll
                for (int nt = 0; nt < 4; nt++)
                    mma16n8k8(acc[mt][nt], af[mt], bf[nt]);
        }
        __syncthreads();   // compute done before next load overwrites this buffer
    }

    // epilogue: direct global stores
    #pragma unroll
    for (int mt = 0; mt < 4; mt++) {
        int r0 = row0 + wm + mt * 16 + g;
        #pragma unroll
        for (int nt = 0; nt < 4; nt++) {
            int cc = col0 + wn + nt * 8 + c * 2;
            if (r0 < M)
                *(float2*)&C[(long long)r0 * NCAT + cc] =
                    make_float2(acc[mt][nt][0], acc[mt][nt][1]);
            if (r0 + 8 < M)
                *(float2*)&C[(long long)(r0 + 8) * NCAT + cc] =
                    make_float2(acc[mt][nt][2], acc[mt][nt][3]);
        }
    }
}

// ---------------- index-width detection (int32 vs int64 dump) ----------------
__global__ void k_detect(const int* ei) {
    __shared__ int found;
    if (threadIdx.x == 0) found = 0;
    __syncthreads();
    for (int i = threadIdx.x; i < 2048; i += blockDim.x)
        if (ei[2 * i + 1] != 0) found = 1;
    __syncthreads();
    if (threadIdx.x == 0) g_is64 = (found == 0) ? 1 : 0;
}
__device__ __forceinline__ int idx_at(const void* p, long long i, int is64) {
    return is64 ? (int)((const long long*)p)[i] : ((const int*)p)[i];
}

// ---------------- edge preprocessing ----------------
__global__ void k_zero_cnt() {
    int i = blockIdx.x * blockDim.x + threadIdx.x;
    if (i < N_NODES * N_REL) g_cnt[i] = 0;
}
__global__ void k_prep(const void* ei, const void* et) {
    int e = blockIdx.x * blockDim.x + threadIdx.x;
    if (e >= N_EDGES) return;
    int is64 = g_is64;
    int s = idx_at(ei, e, is64);
    int d = idx_at(ei, (long long)N_EDGES + e, is64);
    int t = idx_at(et, e, is64);
    g_esrc[e] = s; g_edst[e] = d; g_etyp[e] = t;
    atomicAdd(&g_cnt[d * N_REL + t], 1);
}
__global__ void k_scale() {
    int e = blockIdx.x * blockDim.x + threadIdx.x;
    if (e >= N_EDGES) return;
    int c = g_cnt[g_edst[e] * N_REL + g_etyp[e]];
    g_escl[e] = 1.0f / (float)max(c, 1);
}

// ---------------- weight build (transposed, tf32-rounded): g_Wt[n, k] --------
__global__ void k_buildWt(const float* __restrict__ root,
                          const float* __restrict__ basis,
                          const float* __restrict__ comp, int K) {
    long long i = (long long)blockIdx.x * blockDim.x + threadIdx.x;
    long long tot = (long long)NCAT * K;
    if (i >= tot) return;
    int n = (int)(i / K), k = (int)(i % K);
    float v;
    if (n < 768) {
        v = root[(long long)k * 768 + n];
    } else {
        int r = n / 768 - 1, f = n % 768;
        v = 0.0f;
        #pragma unroll
        for (int b = 0; b < N_BASES; b++)
            v += comp[r * N_BASES + b] * basis[((long long)b * K + k) * 768 + f];
    }
    g_Wt[i] = to_tf32(v);
}

// ---------------- aggregation / pointwise ----------------
__global__ void k_init(float* __restrict__ out, const float* __restrict__ bias) {
    long long i = (long long)blockIdx.x * blockDim.x + threadIdx.x;
    if (i >= (long long)N_NODES * 192) return;
    int f4 = (int)(i % 192);
    long long n = i / 192;
    float4 h = *(const float4*)&g_H[n * NCAT + f4 * 4];
    float4 b = *(const float4*)&bias[f4 * 4];
    h.x += b.x; h.y += b.y; h.z += b.z; h.w += b.w;
    *(float4*)&out[n * 768 + f4 * 4] = h;
}
__global__ void k_scatter(float* __restrict__ out) {
    int e = blockIdx.x;
    int s = g_esrc[e], d = g_edst[e], t = g_etyp[e];
    float scl = g_escl[e];
    float4 v = *(const float4*)&g_H[(long long)s * NCAT + (long long)(1 + t) * 768
                                    + threadIdx.x * 4];
    float* o = &out[(long long)d * 768 + threadIdx.x * 4];
    atomicAdd(o + 0, v.x * scl);
    atomicAdd(o + 1, v.y * scl);
    atomicAdd(o + 2, v.z * scl);
    atomicAdd(o + 3, v.w * scl);
}
__global__ void k_bnrelu(const float* __restrict__ gamma, const float* __restrict__ beta,
                         const float* __restrict__ mean,  const float* __restrict__ var) {
    long long i = (long long)blockIdx.x * blockDim.x + threadIdx.x;
    if (i >= (long long)N_NODES * 192) return;
    int f = (int)(i % 192) * 4;
    float4 v = ((float4*)g_acc)[i];
    float4 r;
    r.x = fmaxf((v.x - mean[f+0]) * rsqrtf(var[f+0] + 1e-5f) * gamma[f+0] + beta[f+0], 0.f);
    r.y = fmaxf((v.y - mean[f+1]) * rsqrtf(var[f+1] + 1e-5f) * gamma[f+1] + beta[f+1], 0.f);
    r.z = fmaxf((v.z - mean[f+2]) * rsqrtf(var[f+2] + 1e-5f) * gamma[f+2] + beta[f+2], 0.f);
    r.w = fmaxf((v.w - mean[f+3]) * rsqrtf(var[f+3] + 1e-5f) * gamma[f+3] + beta[f+3], 0.f);
    ((float4*)g_acc)[i] = r;
}
__global__ void k_l2norm(float* __restrict__ out) {
    int n = blockIdx.x;
    float4 v = *(float4*)&out[(long long)n * 768 + threadIdx.x * 4];
    float ss = v.x*v.x + v.y*v.y + v.z*v.z + v.w*v.w;
    #pragma unroll
    for (int o = 16; o > 0; o >>= 1)
        ss += __shfl_xor_sync(0xffffffffu, ss, o);
    __shared__ float sw[6];
    __shared__ float s_inv;
    int wid = threadIdx.x / 32;
    if ((threadIdx.x & 31) == 0) sw[wid] = ss;
    __syncthreads();
    if (threadIdx.x == 0) {
        float tot = sw[0] + sw[1] + sw[2] + sw[3] + sw[4] + sw[5];
        s_inv = 1.0f / fmaxf(sqrtf(tot), 1e-12f);
    }
    __syncthreads();
    float inv = s_inv;
    v.x *= inv; v.y *= inv; v.z *= inv; v.w *= inv;
    *(float4*)&out[(long long)n * 768 + threadIdx.x * 4] = v;
}

// ---------------- launch ----------------
extern "C" void kernel_launch(void* const* d_in, const int* in_sizes, int n_in,
                              void* d_out, int out_size) {
    const float* x       = (const float*)d_in[0];
    const void*  ei      = d_in[1];
    const void*  et      = d_in[2];
    const float* basis1  = (const float*)d_in[3];
    const float* comp1   = (const float*)d_in[4];
    const float* root1   = (const float*)d_in[5];
    const float* bias1   = (const float*)d_in[6];
    const float* bn_g    = (const float*)d_in[7];
    const float* bn_b    = (const float*)d_in[8];
    const float* bn_m    = (const float*)d_in[9];
    const float* bn_v    = (const float*)d_in[10];
    const float* basis2  = (const float*)d_in[11];
    const float* comp2   = (const float*)d_in[12];
    const float* root2   = (const float*)d_in[13];
    const float* bias2   = (const float*)d_in[14];
    float* out = (float*)d_out;

    float* g_H_p;   cudaGetSymbolAddress((void**)&g_H_p,   g_H);
    float* g_acc_p; cudaGetSymbolAddress((void**)&g_acc_p, g_acc);

    cudaFuncSetAttribute(k_gemm_mma, cudaFuncAttributeMaxDynamicSharedMemorySize, SM_TOTAL);

    const int EB = (N_EDGES + 255) / 256;
    const int PW = (int)(((long long)N_NODES * 192 + 255) / 256);
    dim3 gemm_grid(NCAT / BN, (N_NODES + BM - 1) / BM);

    // edge preprocessing (shared by both layers)
    k_detect<<<1, 256>>>((const int*)ei);
    k_zero_cnt<<<(N_NODES * N_REL + 255) / 256, 256>>>();
    k_prep<<<EB, 256>>>(ei, et);
    k_scale<<<EB, 256>>>();

    // ---- layer 1 ----
    k_buildWt<<<(int)(((long long)NCAT * IN_CH + 255) / 256), 256>>>(root1, basis1, comp1, IN_CH);
    k_gemm_mma<<<gemm_grid, 256, SM_TOTAL>>>(x, g_H_p, N_NODES, IN_CH);
    k_init<<<PW, 256>>>(g_acc_p, bias1);
    k_scatter<<<N_EDGES, 192>>>(g_acc_p);
    k_bnrelu<<<PW, 256>>>(bn_g, bn_b, bn_m, bn_v);

    // ---- layer 2 ----
    k_buildWt<<<(int)(((long long)NCAT * HID + 255) / 256), 256>>>(root2, basis2, comp2, HID);
    k_gemm_mma<<<gemm_grid, 256, SM_TOTAL>>>(g_acc_p, g_H_p, N_NODES, HID);
    k_init<<<PW, 256>>>(out, bias2);
    k_scatter<<<N_EDGES, 192>>>(out);
    k_l2norm<<<N_NODES, 192>>>(out);
}

// round 4
// speedup vs baseline: 2.4814x; 1.2387x over previous
#include <cuda_runtime.h>
#include <cstdint>
#include <math.h>

#define N_NODES 50000
#define N_EDGES 200000
#define IN_CH   256
#define HID     768
#define N_REL   5
#define N_BASES 4
#define NCAT    (6*768)    /* [root | w0..w4] = 4608 GEMM columns */
#define NREL_C  (5*768)    /* relation-only columns stored in g_H  */

// ---------------- static device scratch (no allocations allowed) -------------
__device__ float g_H[(size_t)N_NODES * NREL_C];   // relation blocks only (736 MB)
__device__ float g_acc[(size_t)N_NODES * HID];    // layer-1 out / layer-2 in
__device__ float g_Wt[(size_t)NCAT * HID];        // W^T: [4608, K] K-major, tf32-rounded
__device__ int   g_cnt[N_NODES * N_REL];
__device__ int   g_esrc[N_EDGES];
__device__ int   g_edst[N_EDGES];
__device__ int   g_etyp[N_EDGES];
__device__ float g_escl[N_EDGES];
__device__ int   g_is64;

// ============================ helpers ====================================
__device__ __forceinline__ float to_tf32(float x) {
    float r;
    asm("cvt.rna.tf32.f32 %0, %1;" : "=f"(r) : "f"(x));
    return r;
}
__device__ __forceinline__ void cp16(uint32_t dst, const void* src, int sz) {
    asm volatile("cp.async.cg.shared.global [%0], [%1], 16, %2;"
                 :: "r"(dst), "l"(src), "r"(sz));
}
__device__ __forceinline__ uint32_t smem_u32(const void* p) {
    uint32_t a;
    asm("{ .reg .u64 t; cvta.to.shared.u64 t, %1; cvt.u32.u64 %0, t; }"
        : "=r"(a) : "l"(p));
    return a;
}
__device__ __forceinline__ void mma16n8k8(float* d, const uint32_t* a, const uint32_t* b) {
    asm volatile(
        "mma.sync.aligned.m16n8k8.row.col.f32.tf32.tf32.f32 "
        "{%0,%1,%2,%3}, {%4,%5,%6,%7}, {%8,%9}, {%0,%1,%2,%3};"
        : "+f"(d[0]), "+f"(d[1]), "+f"(d[2]), "+f"(d[3])
        : "r"(a[0]), "r"(a[1]), "r"(a[2]), "r"(a[3]), "r"(b[0]), "r"(b[1]));
}
__device__ __forceinline__ void red_v4(float* addr, float4 v) {
    asm volatile("red.global.add.v4.f32 [%0], {%1,%2,%3,%4};"
                 :: "l"(addr), "f"(v.x), "f"(v.y), "f"(v.z), "f"(v.w) : "memory");
}

// ====================== tf32 mma.sync GEMM ====================================
// Out[M, 4608] = A[M, K] @ g_Wt^T   (g_Wt is [4608, K] K-major)
// cols <768 -> dst[row*768+col] + bias  ;  cols >=768 -> g_H[row*3840 + col-768]
#define BM 128
#define BN 256
#define BK 32
#define AST 36                          /* padded row stride in floats   */
#define SA_BUF (BM * AST)               /* 4608 floats                   */
#define SB_BUF (BN * AST)               /* 9216 floats                   */
#define SM_TOTAL ((2*SA_BUF + 2*SB_BUF) * 4)   /* 110,592 bytes          */

__global__ void __launch_bounds__(256, 1)
k_gemm_mma(const float* __restrict__ A, float* __restrict__ dst,
           const float* __restrict__ bias, int M, int K) {
    extern __shared__ float sm[];
    float* As[2] = { sm,            sm + SA_BUF };
    float* Bs[2] = { sm + 2*SA_BUF, sm + 2*SA_BUF + SB_BUF };

    const int tid  = threadIdx.x;
    const int lane = tid & 31;
    const int warp = tid >> 5;
    const int wm   = (warp & 1) * 64;    // warp offset along M
    const int wn   = (warp >> 1) * 64;   // warp offset along N
    const int row0 = blockIdx.y * BM;
    const int col0 = blockIdx.x * BN;
    const int NIT  = K / BK;

    const int g = lane >> 2;             // fragment row group
    const int c = lane & 3;              // fragment k index

    float acc[4][8][4];
    #pragma unroll
    for (int i = 0; i < 4; i++)
        #pragma unroll
        for (int j = 0; j < 8; j++) {
            acc[i][j][0] = 0.f; acc[i][j][1] = 0.f;
            acc[i][j][2] = 0.f; acc[i][j][3] = 0.f;
        }

    const int lr = tid >> 3;             // base row for 16B chunks (0..31)
    const int lc = (tid & 7) * 4;        // k offset of the 16B chunk

    auto load_buf = [&](int it) {
        const int b  = it & 1;
        const int k0 = it * BK;
        const uint32_t sA = smem_u32(As[b]);
        const uint32_t sB = smem_u32(Bs[b]);
        #pragma unroll
        for (int i = 0; i < 4; i++) {                 // A: 128 rows
            int r = lr + i * 32;
            int grow = row0 + r;
            const float* src = A + (long long)(grow < M ? grow : M - 1) * K + k0 + lc;
            cp16(sA + (r * AST + lc) * 4, src, (grow < M) ? 16 : 0);
        }
        #pragma unroll
        for (int i = 0; i < 8; i++) {                 // B: 256 rows
            int r = lr + i * 32;
            const float* src = g_Wt + (long long)(col0 + r) * K + k0 + lc;
            cp16(sB + (r * AST + lc) * 4, src, 16);
        }
        asm volatile("cp.async.commit_group;" ::: "memory");
    };

    load_buf(0);

    for (int it = 0; it < NIT; it++) {
        if (it + 1 < NIT) {
            load_buf(it + 1);
            asm volatile("cp.async.wait_group 1;" ::: "memory");
        } else {
            asm volatile("cp.async.wait_group 0;" ::: "memory");
        }
        __syncthreads();

        const float* pa = As[it & 1];
        const float* pb = Bs[it & 1];

        #pragma unroll
        for (int ks = 0; ks < BK / 8; ks++) {
            const int kk = ks * 8;
            uint32_t af[4][4], bf[8][2];
            #pragma unroll
            for (int mt = 0; mt < 4; mt++) {
                int r = wm + mt * 16 + g;
                af[mt][0] = __float_as_uint(to_tf32(pa[ r      * AST + kk + c    ]));
                af[mt][1] = __float_as_uint(to_tf32(pa[(r + 8) * AST + kk + c    ]));
                af[mt][2] = __float_as_uint(to_tf32(pa[ r      * AST + kk + c + 4]));
                af[mt][3] = __float_as_uint(to_tf32(pa[(r + 8) * AST + kk + c + 4]));
            }
            #pragma unroll
            for (int nt = 0; nt < 8; nt++) {
                int n = wn + nt * 8 + g;
                bf[nt][0] = __float_as_uint(pb[n * AST + kk + c    ]);
                bf[nt][1] = __float_as_uint(pb[n * AST + kk + c + 4]);
            }
            #pragma unroll
            for (int mt = 0; mt < 4; mt++)
                #pragma unroll
                for (int nt = 0; nt < 8; nt++)
                    mma16n8k8(acc[mt][nt], af[mt], bf[nt]);
        }
        __syncthreads();
    }

    // epilogue: root block -> dst (+bias), relation blocks -> g_H (stride 3840)
    const bool is_root = (col0 < 768);
    #pragma unroll
    for (int mt = 0; mt < 4; mt++) {
        int r0 = row0 + wm + mt * 16 + g;
        #pragma unroll
        for (int nt = 0; nt < 8; nt++) {
            int cc = col0 + wn + nt * 8 + c * 2;
            float2 lo = make_float2(acc[mt][nt][0], acc[mt][nt][1]);
            float2 hi = make_float2(acc[mt][nt][2], acc[mt][nt][3]);
            if (is_root) {
                float2 b = *(const float2*)&bias[cc];
                lo.x += b.x; lo.y += b.y; hi.x += b.x; hi.y += b.y;
                if (r0 < M)     *(float2*)&dst[(long long)r0 * 768 + cc] = lo;
                if (r0 + 8 < M) *(float2*)&dst[(long long)(r0 + 8) * 768 + cc] = hi;
            } else {
                int ch = cc - 768;
                if (r0 < M)     *(float2*)&g_H[(long long)r0 * NREL_C + ch] = lo;
                if (r0 + 8 < M) *(float2*)&g_H[(long long)(r0 + 8) * NREL_C + ch] = hi;
            }
        }
    }
}

// ---------------- index-width detection (int32 vs int64 dump) ----------------
__global__ void k_detect(const int* ei) {
    __shared__ int found;
    if (threadIdx.x == 0) found = 0;
    __syncthreads();
    for (int i = threadIdx.x; i < 2048; i += blockDim.x)
        if (ei[2 * i + 1] != 0) found = 1;
    __syncthreads();
    if (threadIdx.x == 0) g_is64 = (found == 0) ? 1 : 0;
}
__device__ __forceinline__ int idx_at(const void* p, long long i, int is64) {
    return is64 ? (int)((const long long*)p)[i] : ((const int*)p)[i];
}

// ---------------- edge preprocessing ----------------
__global__ void k_zero_cnt() {
    int i = blockIdx.x * blockDim.x + threadIdx.x;
    if (i < N_NODES * N_REL) g_cnt[i] = 0;
}
__global__ void k_prep(const void* ei, const void* et) {
    int e = blockIdx.x * blockDim.x + threadIdx.x;
    if (e >= N_EDGES) return;
    int is64 = g_is64;
    int s = idx_at(ei, e, is64);
    int d = idx_at(ei, (long long)N_EDGES + e, is64);
    int t = idx_at(et, e, is64);
    g_esrc[e] = s; g_edst[e] = d; g_etyp[e] = t;
    atomicAdd(&g_cnt[d * N_REL + t], 1);
}
__global__ void k_scale() {
    int e = blockIdx.x * blockDim.x + threadIdx.x;
    if (e >= N_EDGES) return;
    int c = g_cnt[g_edst[e] * N_REL + g_etyp[e]];
    g_escl[e] = 1.0f / (float)max(c, 1);
}

// ---------------- weight build (transposed, tf32-rounded): g_Wt[n, k] --------
__global__ void k_buildWt(const float* __restrict__ root,
                          const float* __restrict__ basis,
                          const float* __restrict__ comp, int K) {
    long long i = (long long)blockIdx.x * blockDim.x + threadIdx.x;
    long long tot = (long long)NCAT * K;
    if (i >= tot) return;
    int n = (int)(i / K), k = (int)(i % K);
    float v;
    if (n < 768) {
        v = root[(long long)k * 768 + n];
    } else {
        int r = n / 768 - 1, f = n % 768;
        v = 0.0f;
        #pragma unroll
        for (int b = 0; b < N_BASES; b++)
            v += comp[r * N_BASES + b] * basis[((long long)b * K + k) * 768 + f];
    }
    g_Wt[i] = to_tf32(v);
}

// ---------------- aggregation / pointwise ----------------
// one block per edge, 192 threads: out[dst] += g_H[src, type*768 + :] * scale
__global__ void k_scatter(float* __restrict__ out) {
    int e = blockIdx.x;
    int s = g_esrc[e], d = g_edst[e], t = g_etyp[e];
    float scl = g_escl[e];
    float4 v = *(const float4*)&g_H[(long long)s * NREL_C + (long long)t * 768
                                    + threadIdx.x * 4];
    v.x *= scl; v.y *= scl; v.z *= scl; v.w *= scl;
    red_v4(&out[(long long)d * 768 + threadIdx.x * 4], v);
}
__global__ void k_bnrelu(const float* __restrict__ gamma, const float* __restrict__ beta,
                         const float* __restrict__ mean,  const float* __restrict__ var) {
    long long i = (long long)blockIdx.x * blockDim.x + threadIdx.x;
    if (i >= (long long)N_NODES * 192) return;
    int f = (int)(i % 192) * 4;
    float4 v = ((float4*)g_acc)[i];
    float4 r;
    r.x = fmaxf((v.x - mean[f+0]) * rsqrtf(var[f+0] + 1e-5f) * gamma[f+0] + beta[f+0], 0.f);
    r.y = fmaxf((v.y - mean[f+1]) * rsqrtf(var[f+1] + 1e-5f) * gamma[f+1] + beta[f+1], 0.f);
    r.z = fmaxf((v.z - mean[f+2]) * rsqrtf(var[f+2] + 1e-5f) * gamma[f+2] + beta[f+2], 0.f);
    r.w = fmaxf((v.w - mean[f+3]) * rsqrtf(var[f+3] + 1e-5f) * gamma[f+3] + beta[f+3], 0.f);
    ((float4*)g_acc)[i] = r;
}
__global__ void k_l2norm(float* __restrict__ out) {
    int n = blockIdx.x;
    float4 v = *(float4*)&out[(long long)n * 768 + threadIdx.x * 4];
    float ss = v.x*v.x + v.y*v.y + v.z*v.z + v.w*v.w;
    #pragma unroll
    for (int o = 16; o > 0; o >>= 1)
        ss += __shfl_xor_sync(0xffffffffu, ss, o);
    __shared__ float sw[6];
    __shared__ float s_inv;
    int wid = threadIdx.x / 32;
    if ((threadIdx.x & 31) == 0) sw[wid] = ss;
    __syncthreads();
    if (threadIdx.x == 0) {
        float tot = sw[0] + sw[1] + sw[2] + sw[3] + sw[4] + sw[5];
        s_inv = 1.0f / fmaxf(sqrtf(tot), 1e-12f);
    }
    __syncthreads();
    float inv = s_inv;
    v.x *= inv; v.y *= inv; v.z *= inv; v.w *= inv;
    *(float4*)&out[(long long)n * 768 + threadIdx.x * 4] = v;
}

// ---------------- launch ----------------
extern "C" void kernel_launch(void* const* d_in, const int* in_sizes, int n_in,
                              void* d_out, int out_size) {
    const float* x       = (const float*)d_in[0];
    const void*  ei      = d_in[1];
    const void*  et      = d_in[2];
    const float* basis1  = (const float*)d_in[3];
    const float* comp1   = (const float*)d_in[4];
    const float* root1   = (const float*)d_in[5];
    const float* bias1   = (const float*)d_in[6];
    const float* bn_g    = (const float*)d_in[7];
    const float* bn_b    = (const float*)d_in[8];
    const float* bn_m    = (const float*)d_in[9];
    const float* bn_v    = (const float*)d_in[10];
    const float* basis2  = (const float*)d_in[11];
    const float* comp2   = (const float*)d_in[12];
    const float* root2   = (const float*)d_in[13];
    const float* bias2   = (const float*)d_in[14];
    float* out = (float*)d_out;

    float* g_acc_p; cudaGetSymbolAddress((void**)&g_acc_p, g_acc);

    cudaFuncSetAttribute(k_gemm_mma, cudaFuncAttributeMaxDynamicSharedMemorySize, SM_TOTAL);

    const int EB = (N_EDGES + 255) / 256;
    const int PW = (int)(((long long)N_NODES * 192 + 255) / 256);
    dim3 gemm_grid(NCAT / BN, (N_NODES + BM - 1) / BM);

    // edge preprocessing (shared by both layers)
    k_detect<<<1, 256>>>((const int*)ei);
    k_zero_cnt<<<(N_NODES * N_REL + 255) / 256, 256>>>();
    k_prep<<<EB, 256>>>(ei, et);
    k_scale<<<EB, 256>>>();

    // ---- layer 1 ----
    k_buildWt<<<(int)(((long long)NCAT * IN_CH + 255) / 256), 256>>>(root1, basis1, comp1, IN_CH);
    k_gemm_mma<<<gemm_grid, 256, SM_TOTAL>>>(x, g_acc_p, bias1, N_NODES, IN_CH);
    k_scatter<<<N_EDGES, 192>>>(g_acc_p);
    k_bnrelu<<<PW, 256>>>(bn_g, bn_b, bn_m, bn_v);

    // ---- layer 2 ----
    k_buildWt<<<(int)(((long long)NCAT * HID + 255) / 256), 256>>>(root2, basis2, comp2, HID);
    k_gemm_mma<<<gemm_grid, 256, SM_TOTAL>>>(g_acc_p, out, bias2, N_NODES, HID);
    k_scatter<<<N_EDGES, 192>>>(out);
    k_l2norm<<<N_NODES, 192>>>(out);
}

// round 5
// speedup vs baseline: 3.5766x; 1.4414x over previous
#include <cuda_runtime.h>
#include <cuda_fp16.h>
#include <cstdint>
#include <math.h>

#define N_NODES 50000
#define N_EDGES 200000
#define IN_CH   256
#define HID     768
#define N_REL   5
#define N_BASES 4
#define NCAT    (6*768)    /* [root | w0..w4] = 4608 GEMM columns */
#define NREL_C  (5*768)    /* relation-only columns stored in g_H  */

// ---------------- static device scratch (no allocations allowed) -------------
__device__ float  g_H[(size_t)N_NODES * NREL_C];   // relation blocks (736 MB)
__device__ float  g_acc[(size_t)N_NODES * HID];    // layer-1 float accumulator
__device__ __half g_Ah[(size_t)N_NODES * HID];     // half A operand (x, then bnrelu out)
__device__ __half g_Wh[(size_t)NCAT * HID];        // W^T: [4608, K] K-major, half
__device__ int    g_cnt[N_NODES * N_REL];
__device__ int    g_esrc[N_EDGES];
__device__ int    g_edst[N_EDGES];
__device__ int    g_etyp[N_EDGES];
__device__ int    g_is64;

// ============================ helpers ====================================
__device__ __forceinline__ void cp16(uint32_t dst, const void* src, int sz) {
    asm volatile("cp.async.cg.shared.global [%0], [%1], 16, %2;"
                 :: "r"(dst), "l"(src), "r"(sz));
}
__device__ __forceinline__ uint32_t smem_u32(const void* p) {
    uint32_t a;
    asm("{ .reg .u64 t; cvta.to.shared.u64 t, %1; cvt.u32.u64 %0, t; }"
        : "=r"(a) : "l"(p));
    return a;
}
__device__ __forceinline__ void mma16n8k16(float* d, const uint32_t* a, const uint32_t* b) {
    asm volatile(
        "mma.sync.aligned.m16n8k16.row.col.f32.f16.f16.f32 "
        "{%0,%1,%2,%3}, {%4,%5,%6,%7}, {%8,%9}, {%0,%1,%2,%3};"
        : "+f"(d[0]), "+f"(d[1]), "+f"(d[2]), "+f"(d[3])
        : "r"(a[0]), "r"(a[1]), "r"(a[2]), "r"(a[3]), "r"(b[0]), "r"(b[1]));
}
__device__ __forceinline__ void red_v4(float* addr, float4 v) {
    asm volatile("red.global.add.v4.f32 [%0], {%1,%2,%3,%4};"
                 :: "l"(addr), "f"(v.x), "f"(v.y), "f"(v.z), "f"(v.w) : "memory");
}

// ====================== fp16 mma.sync GEMM (fp32 accum) ======================
// Out[M, 4608] = A[M, K] @ g_Wh^T   (g_Wh is [4608, K] K-major, half)
// cols <768 -> dst[row*768+col] + bias ; cols >=768 -> g_H[row*3840 + col-768]
#define BM 128
#define BN 256
#define BK 32
#define AST 40                              /* padded row stride in halves */
#define SA_BUF (BM * AST)                   /* halves */
#define SB_BUF (BN * AST)
#define SM_TOTAL ((2*SA_BUF + 2*SB_BUF) * 2)  /* bytes = 61,440 */

__global__ void __launch_bounds__(256, 1)
k_gemm_mma(const __half* __restrict__ A, float* __restrict__ dst,
           const float* __restrict__ bias, int M, int K) {
    extern __shared__ __half sm[];
    __half* As[2] = { sm,            sm + SA_BUF };
    __half* Bs[2] = { sm + 2*SA_BUF, sm + 2*SA_BUF + SB_BUF };

    const int tid  = threadIdx.x;
    const int lane = tid & 31;
    const int warp = tid >> 5;
    const int wm   = (warp & 1) * 64;     // warp offset along M
    const int wn   = (warp >> 1) * 64;    // warp offset along N
    const int row0 = blockIdx.y * BM;
    const int col0 = blockIdx.x * BN;
    const int NIT  = K / BK;

    const int g = lane >> 2;              // fragment row group (0..7)
    const int c = lane & 3;               // fragment k pair index (0..3)

    float acc[4][8][4];
    #pragma unroll
    for (int i = 0; i < 4; i++)
        #pragma unroll
        for (int j = 0; j < 8; j++) {
            acc[i][j][0] = 0.f; acc[i][j][1] = 0.f;
            acc[i][j][2] = 0.f; acc[i][j][3] = 0.f;
        }

    // cp.async: 16B = 8 halves per chunk; each row of BK=32 halves = 4 chunks
    auto load_buf = [&](int it) {
        const int b  = it & 1;
        const int k0 = it * BK;
        const uint32_t sA = smem_u32(As[b]);
        const uint32_t sB = smem_u32(Bs[b]);
        #pragma unroll
        for (int i = 0; i < 2; i++) {                 // A: 128 rows * 4 chunks
            int q = tid + i * 256;
            int r = q >> 2, ch = q & 3;
            int grow = row0 + r;
            const __half* src = A + (long long)(grow < M ? grow : M - 1) * K + k0 + ch * 8;
            cp16(sA + (r * AST + ch * 8) * 2, src, (grow < M) ? 16 : 0);
        }
        #pragma unroll
        for (int i = 0; i < 4; i++) {                 // B: 256 rows * 4 chunks
            int q = tid + i * 256;
            int r = q >> 2, ch = q & 3;
            const __half* src = g_Wh + (long long)(col0 + r) * K + k0 + ch * 8;
            cp16(sB + (r * AST + ch * 8) * 2, src, 16);
        }
        asm volatile("cp.async.commit_group;" ::: "memory");
    };

    load_buf(0);

    for (int it = 0; it < NIT; it++) {
        if (it + 1 < NIT) {
            load_buf(it + 1);
            asm volatile("cp.async.wait_group 1;" ::: "memory");
        } else {
            asm volatile("cp.async.wait_group 0;" ::: "memory");
        }
        __syncthreads();

        const uint32_t* pa = (const uint32_t*)As[it & 1];   // AST/2 = 20 uints/row
        const uint32_t* pb = (const uint32_t*)Bs[it & 1];

        #pragma unroll
        for (int ks = 0; ks < BK / 16; ks++) {        // 2 k16 steps per BK=32
            const int kk = ks * 8;                    // uint offset within row
            uint32_t af[4][4], bf[8][2];
            #pragma unroll
            for (int mt = 0; mt < 4; mt++) {
                int r = wm + mt * 16 + g;
                af[mt][0] = pa[ r      * 20 + kk + c    ];
                af[mt][1] = pa[(r + 8) * 20 + kk + c    ];
                af[mt][2] = pa[ r      * 20 + kk + c + 4];
                af[mt][3] = pa[(r + 8) * 20 + kk + c + 4];
            }
            #pragma unroll
            for (int nt = 0; nt < 8; nt++) {
                int n = wn + nt * 8 + g;
                bf[nt][0] = pb[n * 20 + kk + c    ];
                bf[nt][1] = pb[n * 20 + kk + c + 4];
            }
            #pragma unroll
            for (int mt = 0; mt < 4; mt++)
                #pragma unroll
                for (int nt = 0; nt < 8; nt++)
                    mma16n8k16(acc[mt][nt], af[mt], bf[nt]);
        }
        __syncthreads();
    }

    // epilogue: root block -> dst (+bias), relation blocks -> g_H (stride 3840)
    const bool is_root = (col0 < 768);
    #pragma unroll
    for (int mt = 0; mt < 4; mt++) {
        int r0 = row0 + wm + mt * 16 + g;
        #pragma unroll
        for (int nt = 0; nt < 8; nt++) {
            int cc = col0 + wn + nt * 8 + c * 2;
            float2 lo = make_float2(acc[mt][nt][0], acc[mt][nt][1]);
            float2 hi = make_float2(acc[mt][nt][2], acc[mt][nt][3]);
            if (is_root) {
                float2 b = *(const float2*)&bias[cc];
                lo.x += b.x; lo.y += b.y; hi.x += b.x; hi.y += b.y;
                if (r0 < M)     *(float2*)&dst[(long long)r0 * 768 + cc] = lo;
                if (r0 + 8 < M) *(float2*)&dst[(long long)(r0 + 8) * 768 + cc] = hi;
            } else {
                int ch = cc - 768;
                if (r0 < M)     *(float2*)&g_H[(long long)r0 * NREL_C + ch] = lo;
                if (r0 + 8 < M) *(float2*)&g_H[(long long)(r0 + 8) * NREL_C + ch] = hi;
            }
        }
    }
}

// ---------------- index-width detection (int32 vs int64 dump) ----------------
__global__ void k_detect(const int* ei) {
    __shared__ int found;
    if (threadIdx.x == 0) found = 0;
    __syncthreads();
    for (int i = threadIdx.x; i < 2048; i += blockDim.x)
        if (ei[2 * i + 1] != 0) found = 1;
    __syncthreads();
    if (threadIdx.x == 0) g_is64 = (found == 0) ? 1 : 0;
}
__device__ __forceinline__ int idx_at(const void* p, long long i, int is64) {
    return is64 ? (int)((const long long*)p)[i] : ((const int*)p)[i];
}

// ---------------- edge preprocessing ----------------
__global__ void k_zero_cnt() {
    int i = blockIdx.x * blockDim.x + threadIdx.x;
    if (i < N_NODES * N_REL) g_cnt[i] = 0;
}
__global__ void k_prep(const void* ei, const void* et) {
    int e = blockIdx.x * blockDim.x + threadIdx.x;
    if (e >= N_EDGES) return;
    int is64 = g_is64;
    int s = idx_at(ei, e, is64);
    int d = idx_at(ei, (long long)N_EDGES + e, is64);
    int t = idx_at(et, e, is64);
    g_esrc[e] = s; g_edst[e] = d; g_etyp[e] = t;
    atomicAdd(&g_cnt[d * N_REL + t], 1);
}

// ---------------- A conversion: float -> half ----------------
__global__ void k_cvtA(const float* __restrict__ x, long long n) {
    long long i = (long long)blockIdx.x * blockDim.x + threadIdx.x;   // half2 units
    if (i >= n / 2) return;
    float2 v = ((const float2*)x)[i];
    ((__half2*)g_Ah)[i] = __floats2half2_rn(v.x, v.y);
}

// ---------------- weight build (transposed, half): g_Wh[n, k] ----------------
__global__ void k_buildWt(const float* __restrict__ root,
                          const float* __restrict__ basis,
                          const float* __restrict__ comp, int K) {
    long long i = (long long)blockIdx.x * blockDim.x + threadIdx.x;
    long long tot = (long long)NCAT * K;
    if (i >= tot) return;
    int n = (int)(i / K), k = (int)(i % K);
    float v;
    if (n < 768) {
        v = root[(long long)k * 768 + n];
    } else {
        int r = n / 768 - 1, f = n % 768;
        v = 0.0f;
        #pragma unroll
        for (int b = 0; b < N_BASES; b++)
            v += comp[r * N_BASES + b] * basis[((long long)b * K + k) * 768 + f];
    }
    g_Wh[i] = __float2half_rn(v);
}

// ---------------- aggregation / pointwise ----------------
// one block per edge, 192 threads: out[dst] += g_H[src, type*768 + :] / cnt
__global__ void k_scatter(float* __restrict__ out) {
    int e = blockIdx.x;
    int s = g_esrc[e], d = g_edst[e], t = g_etyp[e];
    float scl = 1.0f / (float)max(g_cnt[d * N_REL + t], 1);
    float4 v = *(const float4*)&g_H[(long long)s * NREL_C + (long long)t * 768
                                    + threadIdx.x * 4];
    v.x *= scl; v.y *= scl; v.z *= scl; v.w *= scl;
    red_v4(&out[(long long)d * 768 + threadIdx.x * 4], v);
}
// BN(eval) + ReLU; reads g_acc float, writes g_Ah half (layer-2 A operand)
__global__ void k_bnrelu(const float* __restrict__ gamma, const float* __restrict__ beta,
                         const float* __restrict__ mean,  const float* __restrict__ var) {
    long long i = (long long)blockIdx.x * blockDim.x + threadIdx.x;
    if (i >= (long long)N_NODES * 192) return;
    int f = (int)(i % 192) * 4;
    float4 v = ((float4*)g_acc)[i];
    float r0 = fmaxf((v.x - mean[f+0]) * rsqrtf(var[f+0] + 1e-5f) * gamma[f+0] + beta[f+0], 0.f);
    float r1 = fmaxf((v.y - mean[f+1]) * rsqrtf(var[f+1] + 1e-5f) * gamma[f+1] + beta[f+1], 0.f);
    float r2 = fmaxf((v.z - mean[f+2]) * rsqrtf(var[f+2] + 1e-5f) * gamma[f+2] + beta[f+2], 0.f);
    float r3 = fmaxf((v.w - mean[f+3]) * rsqrtf(var[f+3] + 1e-5f) * gamma[f+3] + beta[f+3], 0.f);
    __half2* dst = (__half2*)&g_Ah[i * 4];
    dst[0] = __floats2half2_rn(r0, r1);
    dst[1] = __floats2half2_rn(r2, r3);
}
__global__ void k_l2norm(float* __restrict__ out) {
    int n = blockIdx.x;
    float4 v = *(float4*)&out[(long long)n * 768 + threadIdx.x * 4];
    float ss = v.x*v.x + v.y*v.y + v.z*v.z + v.w*v.w;
    #pragma unroll
    for (int o = 16; o > 0; o >>= 1)
        ss += __shfl_xor_sync(0xffffffffu, ss, o);
    __shared__ float sw[6];
    __shared__ float s_inv;
    int wid = threadIdx.x / 32;
    if ((threadIdx.x & 31) == 0) sw[wid] = ss;
    __syncthreads();
    if (threadIdx.x == 0) {
        float tot = sw[0] + sw[1] + sw[2] + sw[3] + sw[4] + sw[5];
        s_inv = 1.0f / fmaxf(sqrtf(tot), 1e-12f);
    }
    __syncthreads();
    float inv = s_inv;
    v.x *= inv; v.y *= inv; v.z *= inv; v.w *= inv;
    *(float4*)&out[(long long)n * 768 + threadIdx.x * 4] = v;
}

// ---------------- launch ----------------
extern "C" void kernel_launch(void* const* d_in, const int* in_sizes, int n_in,
                              void* d_out, int out_size) {
    const float* x       = (const float*)d_in[0];
    const void*  ei      = d_in[1];
    const void*  et      = d_in[2];
    const float* basis1  = (const float*)d_in[3];
    const float* comp1   = (const float*)d_in[4];
    const float* root1   = (const float*)d_in[5];
    const float* bias1   = (const float*)d_in[6];
    const float* bn_g    = (const float*)d_in[7];
    const float* bn_b    = (const float*)d_in[8];
    const float* bn_m    = (const float*)d_in[9];
    const float* bn_v    = (const float*)d_in[10];
    const float* basis2  = (const float*)d_in[11];
    const float* comp2   = (const float*)d_in[12];
    const float* root2   = (const float*)d_in[13];
    const float* bias2   = (const float*)d_in[14];
    float* out = (float*)d_out;

    float*  g_acc_p; cudaGetSymbolAddress((void**)&g_acc_p, g_acc);
    __half* g_Ah_p;  cudaGetSymbolAddress((void**)&g_Ah_p,  g_Ah);

    cudaFuncSetAttribute(k_gemm_mma, cudaFuncAttributeMaxDynamicSharedMemorySize, SM_TOTAL);

    const int EB = (N_EDGES + 255) / 256;
    const int PW = (int)(((long long)N_NODES * 192 + 255) / 256);
    dim3 gemm_grid(NCAT / BN, (N_NODES + BM - 1) / BM);

    // edge preprocessing (shared by both layers)
    k_detect<<<1, 256>>>((const int*)ei);
    k_zero_cnt<<<(N_NODES * N_REL + 255) / 256, 256>>>();
    k_prep<<<EB, 256>>>(ei, et);

    // ---- layer 1 ----
    k_cvtA<<<(int)(((long long)N_NODES * IN_CH / 2 + 255) / 256), 256>>>(x, (long long)N_NODES * IN_CH);
    k_buildWt<<<(int)(((long long)NCAT * IN_CH + 255) / 256), 256>>>(root1, basis1, comp1, IN_CH);
    k_gemm_mma<<<gemm_grid, 256, SM_TOTAL>>>(g_Ah_p, g_acc_p, bias1, N_NODES, IN_CH);
    k_scatter<<<N_EDGES, 192>>>(g_acc_p);
    k_bnrelu<<<PW, 256>>>(bn_g, bn_b, bn_m, bn_v);

    // ---- layer 2 ----
    k_buildWt<<<(int)(((long long)NCAT * HID + 255) / 256), 256>>>(root2, basis2, comp2, HID);
    k_gemm_mma<<<gemm_grid, 256, SM_TOTAL>>>(g_Ah_p, out, bias2, N_NODES, HID);
    k_scatter<<<N_EDGES, 192>>>(out);
    k_l2norm<<<N_NODES, 192>>>(out);
}

// round 6
// speedup vs baseline: 4.2434x; 1.1864x over previous
#include <cuda_runtime.h>
#include <cuda_fp16.h>
#include <cstdint>
#include <math.h>

#define N_NODES 50000
#define N_EDGES 200000
#define IN_CH   256
#define HID     768
#define N_REL   5
#define N_BASES 4
#define NCAT    (6*768)    /* [root | w0..w4] = 4608 GEMM columns */
#define NREL_C  (5*768)    /* relation-only columns stored in g_Hh */

// ---------------- static device scratch (no allocations allowed) -------------
__device__ __half g_Hh[(size_t)N_NODES * NREL_C];  // relation blocks, half (368 MB)
__device__ float  g_acc[(size_t)N_NODES * HID];    // layer-1 float accumulator
__device__ __half g_Ah[(size_t)N_NODES * HID];     // half A operand
__device__ __half g_Wh[(size_t)NCAT * HID];        // W^T: [4608, K] K-major, half
__device__ int    g_cnt[N_NODES * N_REL];
__device__ int    g_deg[N_NODES];
__device__ int    g_off[N_NODES + 1];
__device__ int    g_pos[N_NODES];
__device__ int    g_eid[N_EDGES];
__device__ int    g_esrc[N_EDGES];
__device__ int    g_edst[N_EDGES];
__device__ int    g_etyp[N_EDGES];
__device__ int    g_is64;

// ============================ helpers ====================================
__device__ __forceinline__ void cp16(uint32_t dst, const void* src, int sz) {
    asm volatile("cp.async.cg.shared.global [%0], [%1], 16, %2;"
                 :: "r"(dst), "l"(src), "r"(sz));
}
__device__ __forceinline__ uint32_t smem_u32(const void* p) {
    uint32_t a;
    asm("{ .reg .u64 t; cvta.to.shared.u64 t, %1; cvt.u32.u64 %0, t; }"
        : "=r"(a) : "l"(p));
    return a;
}
__device__ __forceinline__ void mma16n8k16(float* d, const uint32_t* a, const uint32_t* b) {
    asm volatile(
        "mma.sync.aligned.m16n8k16.row.col.f32.f16.f16.f32 "
        "{%0,%1,%2,%3}, {%4,%5,%6,%7}, {%8,%9}, {%0,%1,%2,%3};"
        : "+f"(d[0]), "+f"(d[1]), "+f"(d[2]), "+f"(d[3])
        : "r"(a[0]), "r"(a[1]), "r"(a[2]), "r"(a[3]), "r"(b[0]), "r"(b[1]));
}
__device__ __forceinline__ void ldsm4(uint32_t& r0, uint32_t& r1, uint32_t& r2,
                                      uint32_t& r3, uint32_t addr) {
    asm volatile("ldmatrix.sync.aligned.m8n8.x4.shared.b16 {%0,%1,%2,%3}, [%4];"
                 : "=r"(r0), "=r"(r1), "=r"(r2), "=r"(r3) : "r"(addr));
}

// ====================== fp16 mma.sync GEMM (fp32 accum) ======================
// Out[M, 4608] = A[M, K] @ g_Wh^T    (g_Wh is [4608, K] K-major, half)
// cols <768 -> dst[row*768+col] + bias ; cols >=768 -> g_Hh (half, stride 3840)
#define BM 128
#define BN 256
#define BK 32
#define AST 40                              /* padded row stride in halves */
#define SA_BUF (BM * AST)                   /* 5120 halves  */
#define SB_BUF (BN * AST)                   /* 10240 halves */
#define STAGES 3
#define SM_TOTAL (STAGES * (SA_BUF + SB_BUF) * 2)   /* 92160 bytes */

__global__ void __launch_bounds__(256, 1)
k_gemm_mma(const __half* __restrict__ A, float* __restrict__ dst,
           const float* __restrict__ bias, int M, int K) {
    extern __shared__ __half sm[];
    const uint32_t sb = smem_u32(sm);
    const uint32_t stb = (SA_BUF + SB_BUF) * 2;       // bytes per stage

    const int tid  = threadIdx.x;
    const int lane = tid & 31;
    const int warp = tid >> 5;
    const int wm   = (warp & 1) * 64;
    const int wn   = (warp >> 1) * 64;
    const int row0 = blockIdx.y * BM;
    const int col0 = blockIdx.x * BN;
    const int NIT  = K / BK;

    const int g = lane >> 2;
    const int c = lane & 3;

    // ldmatrix per-lane byte offsets (within a stage buffer)
    const uint32_t a_off = (((lane & 15) * AST) + ((lane >> 4) * 8)) * 2;
    const uint32_t b_off = ((((lane & 7) + ((lane >> 4) << 3)) * AST)
                            + (((lane >> 3) & 1) * 8)) * 2;

    float acc[4][8][4];
    #pragma unroll
    for (int i = 0; i < 4; i++)
        #pragma unroll
        for (int j = 0; j < 8; j++) {
            acc[i][j][0] = 0.f; acc[i][j][1] = 0.f;
            acc[i][j][2] = 0.f; acc[i][j][3] = 0.f;
        }

    auto load_buf = [&](int it) {
        const int st = it % STAGES;
        const int k0 = it * BK;
        const uint32_t sA = sb + st * stb;
        const uint32_t sB = sA + SA_BUF * 2;
        #pragma unroll
        for (int i = 0; i < 2; i++) {                 // A: 128 rows * 4 chunks
            int q = tid + i * 256;
            int r = q >> 2, ch = q & 3;
            int grow = row0 + r;
            const __half* src = A + (long long)(grow < M ? grow : M - 1) * K + k0 + ch * 8;
            cp16(sA + (r * AST + ch * 8) * 2, src, (grow < M) ? 16 : 0);
        }
        #pragma unroll
        for (int i = 0; i < 4; i++) {                 // B: 256 rows * 4 chunks
            int q = tid + i * 256;
            int r = q >> 2, ch = q & 3;
            const __half* src = g_Wh + (long long)(col0 + r) * K + k0 + ch * 8;
            cp16(sB + (r * AST + ch * 8) * 2, src, 16);
        }
        asm volatile("cp.async.commit_group;" ::: "memory");
    };

    load_buf(0);
    load_buf(1);

    for (int it = 0; it < NIT; it++) {
        if (it + 1 < NIT)
            asm volatile("cp.async.wait_group 1;" ::: "memory");
        else
            asm volatile("cp.async.wait_group 0;" ::: "memory");
        __syncthreads();
        if (it + 2 < NIT) load_buf(it + 2);

        const int st = it % STAGES;
        const uint32_t sA = sb + st * stb;
        const uint32_t sB = sA + SA_BUF * 2;

        #pragma unroll
        for (int ks = 0; ks < 2; ks++) {              // 2 x k16 per BK=32
            uint32_t af[4][4], bf[8][2];
            #pragma unroll
            for (int mt = 0; mt < 4; mt++)
                ldsm4(af[mt][0], af[mt][1], af[mt][2], af[mt][3],
                      sA + a_off + (uint32_t)((wm + mt * 16) * AST * 2) + ks * 32);
            #pragma unroll
            for (int p = 0; p < 4; p++)
                ldsm4(bf[2*p][0], bf[2*p][1], bf[2*p+1][0], bf[2*p+1][1],
                      sB + b_off + (uint32_t)((wn + p * 16) * AST * 2) + ks * 32);
            #pragma unroll
            for (int mt = 0; mt < 4; mt++)
                #pragma unroll
                for (int nt = 0; nt < 8; nt++)
                    mma16n8k16(acc[mt][nt], af[mt], bf[nt]);
        }
    }

    // epilogue: root block -> dst (+bias), relation blocks -> g_Hh (half)
    const bool is_root = (col0 < 768);
    #pragma unroll
    for (int mt = 0; mt < 4; mt++) {
        int r0 = row0 + wm + mt * 16 + g;
        #pragma unroll
        for (int nt = 0; nt < 8; nt++) {
            int cc = col0 + wn + nt * 8 + c * 2;
            if (is_root) {
                float2 b = *(const float2*)&bias[cc];
                if (r0 < M)
                    *(float2*)&dst[(long long)r0 * 768 + cc] =
                        make_float2(acc[mt][nt][0] + b.x, acc[mt][nt][1] + b.y);
                if (r0 + 8 < M)
                    *(float2*)&dst[(long long)(r0 + 8) * 768 + cc] =
                        make_float2(acc[mt][nt][2] + b.x, acc[mt][nt][3] + b.y);
            } else {
                int ch = cc - 768;
                if (r0 < M)
                    *(__half2*)&g_Hh[(long long)r0 * NREL_C + ch] =
                        __floats2half2_rn(acc[mt][nt][0], acc[mt][nt][1]);
                if (r0 + 8 < M)
                    *(__half2*)&g_Hh[(long long)(r0 + 8) * NREL_C + ch] =
                        __floats2half2_rn(acc[mt][nt][2], acc[mt][nt][3]);
            }
        }
    }
}

// ---------------- index-width detection (int32 vs int64 dump) ----------------
__global__ void k_detect(const int* ei) {
    __shared__ int found;
    if (threadIdx.x == 0) found = 0;
    __syncthreads();
    for (int i = threadIdx.x; i < 2048; i += blockDim.x)
        if (ei[2 * i + 1] != 0) found = 1;
    __syncthreads();
    if (threadIdx.x == 0) g_is64 = (found == 0) ? 1 : 0;
}
__device__ __forceinline__ int idx_at(const void* p, long long i, int is64) {
    return is64 ? (int)((const long long*)p)[i] : ((const int*)p)[i];
}

// ---------------- edge preprocessing / CSR build ----------------
__global__ void k_zero() {
    int i = blockIdx.x * blockDim.x + threadIdx.x;
    if (i < N_NODES * N_REL) g_cnt[i] = 0;
    if (i < N_NODES) g_deg[i] = 0;
}
__global__ void k_prep(const void* ei, const void* et) {
    int e = blockIdx.x * blockDim.x + threadIdx.x;
    if (e >= N_EDGES) return;
    int is64 = g_is64;
    int s = idx_at(ei, e, is64);
    int d = idx_at(ei, (long long)N_EDGES + e, is64);
    int t = idx_at(et, e, is64);
    g_esrc[e] = s; g_edst[e] = d; g_etyp[e] = t;
    atomicAdd(&g_cnt[d * N_REL + t], 1);
    atomicAdd(&g_deg[d], 1);
}
// single-block exclusive scan of g_deg -> g_off; zeroes g_pos
__global__ void k_scan() {
    const int tid = threadIdx.x, lane = tid & 31, wid = tid >> 5;
    __shared__ int wsum[32];
    __shared__ int carry;
    if (tid == 0) carry = 0;
    __syncthreads();
    for (int base = 0; base < N_NODES; base += 1024) {
        int i = base + tid;
        int v = (i < N_NODES) ? g_deg[i] : 0;
        int x = v;
        #pragma unroll
        for (int o = 1; o < 32; o <<= 1) {
            int y = __shfl_up_sync(0xffffffffu, x, o);
            if (lane >= o) x += y;
        }
        if (lane == 31) wsum[wid] = x;
        __syncthreads();
        if (wid == 0) {
            int s = wsum[lane];
            #pragma unroll
            for (int o = 1; o < 32; o <<= 1) {
                int y = __shfl_up_sync(0xffffffffu, s, o);
                if (lane >= o) s += y;
            }
            wsum[lane] = s;
        }
        __syncthreads();
        int excl = carry + x - v + (wid ? wsum[wid - 1] : 0);
        if (i < N_NODES) { g_off[i] = excl; g_pos[i] = 0; }
        int tot = wsum[31];
        __syncthreads();
        if (tid == 0) carry += tot;
        __syncthreads();
    }
    if (threadIdx.x == 0) g_off[N_NODES] = carry;
}
__global__ void k_fill() {
    int e = blockIdx.x * blockDim.x + threadIdx.x;
    if (e >= N_EDGES) return;
    int d = g_edst[e];
    int p = atomicAdd(&g_pos[d], 1);
    g_eid[g_off[d] + p] = e;
}

// ---------------- A conversion: float -> half ----------------
__global__ void k_cvtA(const float* __restrict__ x, long long n) {
    long long i = (long long)blockIdx.x * blockDim.x + threadIdx.x;
    if (i >= n / 2) return;
    float2 v = ((const float2*)x)[i];
    ((__half2*)g_Ah)[i] = __floats2half2_rn(v.x, v.y);
}

// ---------------- weight build (transposed, half): g_Wh[n, k] ----------------
__global__ void k_buildWt(const float* __restrict__ root,
                          const float* __restrict__ basis,
                          const float* __restrict__ comp, int K) {
    long long i = (long long)blockIdx.x * blockDim.x + threadIdx.x;
    long long tot = (long long)NCAT * K;
    if (i >= tot) return;
    int n = (int)(i / K), k = (int)(i % K);
    float v;
    if (n < 768) {
        v = root[(long long)k * 768 + n];
    } else {
        int r = n / 768 - 1, f = n % 768;
        v = 0.0f;
        #pragma unroll
        for (int b = 0; b < N_BASES; b++)
            v += comp[r * N_BASES + b] * basis[((long long)b * K + k) * 768 + f];
    }
    g_Wh[i] = __float2half_rn(v);
}

// ---------------- aggregation (CSR gather, no atomics) ----------------
// one block (192 threads) per dst node: out[n] += sum_e g_Hh[src_e, t_e]/cnt
__global__ void k_agg(float* __restrict__ out) {
    int n = blockIdx.x;
    int beg = g_off[n], end = g_off[n + 1];
    if (beg == end) return;
    int tid = threadIdx.x;
    float4 a = *(float4*)&out[(long long)n * 768 + tid * 4];
    for (int j = beg; j < end; j++) {
        int e = g_eid[j];
        int s = g_esrc[e], t = g_etyp[e];
        float scl = 1.0f / (float)g_cnt[n * N_REL + t];
        const __half2* h = (const __half2*)&g_Hh[(size_t)s * NREL_C
                                                 + (size_t)t * 768 + tid * 4];
        float2 f0 = __half22float2(h[0]);
        float2 f1 = __half22float2(h[1]);
        a.x = fmaf(f0.x, scl, a.x);
        a.y = fmaf(f0.y, scl, a.y);
        a.z = fmaf(f1.x, scl, a.z);
        a.w = fmaf(f1.y, scl, a.w);
    }
    *(float4*)&out[(long long)n * 768 + tid * 4] = a;
}

// BN(eval) + ReLU; reads g_acc float, writes g_Ah half (layer-2 A operand)
__global__ void k_bnrelu(const float* __restrict__ gamma, const float* __restrict__ beta,
                         const float* __restrict__ mean,  const float* __restrict__ var) {
    long long i = (long long)blockIdx.x * blockDim.x + threadIdx.x;
    if (i >= (long long)N_NODES * 192) return;
    int f = (int)(i % 192) * 4;
    float4 v = ((float4*)g_acc)[i];
    float r0 = fmaxf((v.x - mean[f+0]) * rsqrtf(var[f+0] + 1e-5f) * gamma[f+0] + beta[f+0], 0.f);
    float r1 = fmaxf((v.y - mean[f+1]) * rsqrtf(var[f+1] + 1e-5f) * gamma[f+1] + beta[f+1], 0.f);
    float r2 = fmaxf((v.z - mean[f+2]) * rsqrtf(var[f+2] + 1e-5f) * gamma[f+2] + beta[f+2], 0.f);
    float r3 = fmaxf((v.w - mean[f+3]) * rsqrtf(var[f+3] + 1e-5f) * gamma[f+3] + beta[f+3], 0.f);
    __half2* dst = (__half2*)&g_Ah[i * 4];
    dst[0] = __floats2half2_rn(r0, r1);
    dst[1] = __floats2half2_rn(r2, r3);
}
__global__ void k_l2norm(float* __restrict__ out) {
    int n = blockIdx.x;
    float4 v = *(float4*)&out[(long long)n * 768 + threadIdx.x * 4];
    float ss = v.x*v.x + v.y*v.y + v.z*v.z + v.w*v.w;
    #pragma unroll
    for (int o = 16; o > 0; o >>= 1)
        ss += __shfl_xor_sync(0xffffffffu, ss, o);
    __shared__ float sw[6];
    __shared__ float s_inv;
    int wid = threadIdx.x / 32;
    if ((threadIdx.x & 31) == 0) sw[wid] = ss;
    __syncthreads();
    if (threadIdx.x == 0) {
        float tot = sw[0] + sw[1] + sw[2] + sw[3] + sw[4] + sw[5];
        s_inv = 1.0f / fmaxf(sqrtf(tot), 1e-12f);
    }
    __syncthreads();
    float inv = s_inv;
    v.x *= inv; v.y *= inv; v.z *= inv; v.w *= inv;
    *(float4*)&out[(long long)n * 768 + threadIdx.x * 4] = v;
}

// ---------------- launch ----------------
extern "C" void kernel_launch(void* const* d_in, const int* in_sizes, int n_in,
                              void* d_out, int out_size) {
    const float* x       = (const float*)d_in[0];
    const void*  ei      = d_in[1];
    const void*  et      = d_in[2];
    const float* basis1  = (const float*)d_in[3];
    const float* comp1   = (const float*)d_in[4];
    const float* root1   = (const float*)d_in[5];
    const float* bias1   = (const float*)d_in[6];
    const float* bn_g    = (const float*)d_in[7];
    const float* bn_b    = (const float*)d_in[8];
    const float* bn_m    = (const float*)d_in[9];
    const float* bn_v    = (const float*)d_in[10];
    const float* basis2  = (const float*)d_in[11];
    const float* comp2   = (const float*)d_in[12];
    const float* root2   = (const float*)d_in[13];
    const float* bias2   = (const float*)d_in[14];
    float* out = (float*)d_out;

    float*  g_acc_p; cudaGetSymbolAddress((void**)&g_acc_p, g_acc);
    __half* g_Ah_p;  cudaGetSymbolAddress((void**)&g_Ah_p,  g_Ah);

    cudaFuncSetAttribute(k_gemm_mma, cudaFuncAttributeMaxDynamicSharedMemorySize, SM_TOTAL);

    const int EB = (N_EDGES + 255) / 256;
    const int PW = (int)(((long long)N_NODES * 192 + 255) / 256);
    dim3 gemm_grid(NCAT / BN, (N_NODES + BM - 1) / BM);

    // edge preprocessing + CSR build (shared by both layers)
    k_detect<<<1, 256>>>((const int*)ei);
    k_zero<<<(N_NODES * N_REL + 255) / 256, 256>>>();
    k_prep<<<EB, 256>>>(ei, et);
    k_scan<<<1, 1024>>>();
    k_fill<<<EB, 256>>>();

    // ---- layer 1 ----
    k_cvtA<<<(int)(((long long)N_NODES * IN_CH / 2 + 255) / 256), 256>>>(x, (long long)N_NODES * IN_CH);
    k_buildWt<<<(int)(((long long)NCAT * IN_CH + 255) / 256), 256>>>(root1, basis1, comp1, IN_CH);
    k_gemm_mma<<<gemm_grid, 256, SM_TOTAL>>>(g_Ah_p, g_acc_p, bias1, N_NODES, IN_CH);
    k_agg<<<N_NODES, 192>>>(g_acc_p);
    k_bnrelu<<<PW, 256>>>(bn_g, bn_b, bn_m, bn_v);

    // ---- layer 2 ----
    k_buildWt<<<(int)(((long long)NCAT * HID + 255) / 256), 256>>>(root2, basis2, comp2, HID);
    k_gemm_mma<<<gemm_grid, 256, SM_TOTAL>>>(g_Ah_p, out, bias2, N_NODES, HID);
    k_agg<<<N_NODES, 192>>>(out);
    k_l2norm<<<N_NODES, 192>>>(out);
}

// round 7
// speedup vs baseline: 5.7628x; 1.3580x over previous
#include <cuda_runtime.h>
#include <cuda_fp16.h>
#include <cstdint>
#include <math.h>

#define N_NODES 50000
#define N_EDGES 200000
#define IN_CH   256
#define HID     768
#define N_REL   5
#define N_BASES 4
#define K1      (5*IN_CH)   /* 1280: [x | Z0..Z3] layer 1 */
#define K2      (5*HID)     /* 3840: [h | Z0..Z3] layer 2 */

// ---------------- static device scratch (no allocations allowed) -------------
__device__ __half g_A1[(size_t)N_NODES * K1];   // layer-1 GEMM A operand (122 MB)
__device__ __half g_A2[(size_t)N_NODES * K2];   // layer-2 GEMM A operand (366 MB)
__device__ float  g_acc[(size_t)N_NODES * HID]; // layer-1 float output
__device__ __half g_Wh[(size_t)HID * K2];       // B^T: [768, K] K-major, half
__device__ int    g_cnt[N_NODES * N_REL];
__device__ int    g_deg[N_NODES];
__device__ int    g_off[N_NODES + 1];
__device__ int    g_pos[N_NODES];
__device__ int    g_eid[N_EDGES];
__device__ int    g_esrc[N_EDGES];
__device__ int    g_edst[N_EDGES];
__device__ int    g_etyp[N_EDGES];
__device__ int    g_is64;

// ============================ helpers ====================================
__device__ __forceinline__ void cp16(uint32_t dst, const void* src, int sz) {
    asm volatile("cp.async.cg.shared.global [%0], [%1], 16, %2;"
                 :: "r"(dst), "l"(src), "r"(sz));
}
__device__ __forceinline__ uint32_t smem_u32(const void* p) {
    uint32_t a;
    asm("{ .reg .u64 t; cvta.to.shared.u64 t, %1; cvt.u32.u64 %0, t; }"
        : "=r"(a) : "l"(p));
    return a;
}
__device__ __forceinline__ void mma16n8k16(float* d, const uint32_t* a, const uint32_t* b) {
    asm volatile(
        "mma.sync.aligned.m16n8k16.row.col.f32.f16.f16.f32 "
        "{%0,%1,%2,%3}, {%4,%5,%6,%7}, {%8,%9}, {%0,%1,%2,%3};"
        : "+f"(d[0]), "+f"(d[1]), "+f"(d[2]), "+f"(d[3])
        : "r"(a[0]), "r"(a[1]), "r"(a[2]), "r"(a[3]), "r"(b[0]), "r"(b[1]));
}
__device__ __forceinline__ void ldsm4(uint32_t& r0, uint32_t& r1, uint32_t& r2,
                                      uint32_t& r3, uint32_t addr) {
    asm volatile("ldmatrix.sync.aligned.m8n8.x4.shared.b16 {%0,%1,%2,%3}, [%4];"
                 : "=r"(r0), "=r"(r1), "=r"(r2), "=r"(r3) : "r"(addr));
}

// ====================== fp16 mma.sync GEMM (fp32 accum) ======================
// dst[M, 768] = A[M, K] @ g_Wh^T + bias   (g_Wh is [768, K] K-major, half)
#define BM 128
#define BN 256
#define BK 32
#define AST 40                              /* padded row stride in halves */
#define SA_BUF (BM * AST)
#define SB_BUF (BN * AST)
#define STAGES 3
#define SM_TOTAL (STAGES * (SA_BUF + SB_BUF) * 2)   /* 92160 bytes */

__global__ void __launch_bounds__(256, 1)
k_gemm_mma(const __half* __restrict__ A, float* __restrict__ dst,
           const float* __restrict__ bias, int M, int K) {
    extern __shared__ __half sm[];
    const uint32_t sb = smem_u32(sm);
    const uint32_t stb = (SA_BUF + SB_BUF) * 2;

    const int tid  = threadIdx.x;
    const int lane = tid & 31;
    const int warp = tid >> 5;
    const int wm   = (warp & 1) * 64;
    const int wn   = (warp >> 1) * 64;
    const int row0 = blockIdx.y * BM;
    const int col0 = blockIdx.x * BN;
    const int NIT  = K / BK;

    const int g = lane >> 2;
    const int c = lane & 3;

    const uint32_t a_off = (((lane & 15) * AST) + ((lane >> 4) * 8)) * 2;
    const uint32_t b_off = ((((lane & 7) + ((lane >> 4) << 3)) * AST)
                            + (((lane >> 3) & 1) * 8)) * 2;

    float acc[4][8][4];
    #pragma unroll
    for (int i = 0; i < 4; i++)
        #pragma unroll
        for (int j = 0; j < 8; j++) {
            acc[i][j][0] = 0.f; acc[i][j][1] = 0.f;
            acc[i][j][2] = 0.f; acc[i][j][3] = 0.f;
        }

    auto load_buf = [&](int it) {
        const int st = it % STAGES;
        const int k0 = it * BK;
        const uint32_t sA = sb + st * stb;
        const uint32_t sB = sA + SA_BUF * 2;
        #pragma unroll
        for (int i = 0; i < 2; i++) {
            int q = tid + i * 256;
            int r = q >> 2, ch = q & 3;
            int grow = row0 + r;
            const __half* src = A + (long long)(grow < M ? grow : M - 1) * K + k0 + ch * 8;
            cp16(sA + (r * AST + ch * 8) * 2, src, (grow < M) ? 16 : 0);
        }
        #pragma unroll
        for (int i = 0; i < 4; i++) {
            int q = tid + i * 256;
            int r = q >> 2, ch = q & 3;
            const __half* src = g_Wh + (long long)(col0 + r) * K + k0 + ch * 8;
            cp16(sB + (r * AST + ch * 8) * 2, src, 16);
        }
        asm volatile("cp.async.commit_group;" ::: "memory");
    };

    load_buf(0);
    load_buf(1);

    for (int it = 0; it < NIT; it++) {
        if (it + 1 < NIT)
            asm volatile("cp.async.wait_group 1;" ::: "memory");
        else
            asm volatile("cp.async.wait_group 0;" ::: "memory");
        __syncthreads();
        if (it + 2 < NIT) load_buf(it + 2);

        const int st = it % STAGES;
        const uint32_t sA = sb + st * stb;
        const uint32_t sB = sA + SA_BUF * 2;

        #pragma unroll
        for (int ks = 0; ks < 2; ks++) {
            uint32_t af[4][4], bf[8][2];
            #pragma unroll
            for (int mt = 0; mt < 4; mt++)
                ldsm4(af[mt][0], af[mt][1], af[mt][2], af[mt][3],
                      sA + a_off + (uint32_t)((wm + mt * 16) * AST * 2) + ks * 32);
            #pragma unroll
            for (int p = 0; p < 4; p++)
                ldsm4(bf[2*p][0], bf[2*p][1], bf[2*p+1][0], bf[2*p+1][1],
                      sB + b_off + (uint32_t)((wn + p * 16) * AST * 2) + ks * 32);
            #pragma unroll
            for (int mt = 0; mt < 4; mt++)
                #pragma unroll
                for (int nt = 0; nt < 8; nt++)
                    mma16n8k16(acc[mt][nt], af[mt], bf[nt]);
        }
    }

    #pragma unroll
    for (int mt = 0; mt < 4; mt++) {
        int r0 = row0 + wm + mt * 16 + g;
        #pragma unroll
        for (int nt = 0; nt < 8; nt++) {
            int cc = col0 + wn + nt * 8 + c * 2;
            float2 b = *(const float2*)&bias[cc];
            if (r0 < M)
                *(float2*)&dst[(long long)r0 * 768 + cc] =
                    make_float2(acc[mt][nt][0] + b.x, acc[mt][nt][1] + b.y);
            if (r0 + 8 < M)
                *(float2*)&dst[(long long)(r0 + 8) * 768 + cc] =
                    make_float2(acc[mt][nt][2] + b.x, acc[mt][nt][3] + b.y);
        }
    }
}

// ---------------- index-width detection (int32 vs int64 dump) ----------------
__global__ void k_detect(const int* ei) {
    __shared__ int found;
    if (threadIdx.x == 0) found = 0;
    __syncthreads();
    for (int i = threadIdx.x; i < 2048; i += blockDim.x)
        if (ei[2 * i + 1] != 0) found = 1;
    __syncthreads();
    if (threadIdx.x == 0) g_is64 = (found == 0) ? 1 : 0;
}
__device__ __forceinline__ int idx_at(const void* p, long long i, int is64) {
    return is64 ? (int)((const long long*)p)[i] : ((const int*)p)[i];
}

// ---------------- edge preprocessing / CSR build ----------------
__global__ void k_zero() {
    int i = blockIdx.x * blockDim.x + threadIdx.x;
    if (i < N_NODES * N_REL) g_cnt[i] = 0;
    if (i < N_NODES) g_deg[i] = 0;
}
__global__ void k_prep(const void* ei, const void* et) {
    int e = blockIdx.x * blockDim.x + threadIdx.x;
    if (e >= N_EDGES) return;
    int is64 = g_is64;
    int s = idx_at(ei, e, is64);
    int d = idx_at(ei, (long long)N_EDGES + e, is64);
    int t = idx_at(et, e, is64);
    g_esrc[e] = s; g_edst[e] = d; g_etyp[e] = t;
    atomicAdd(&g_cnt[d * N_REL + t], 1);
    atomicAdd(&g_deg[d], 1);
}
// single-block exclusive scan of g_deg -> g_off (4 elems/thread); zeroes g_pos
__global__ void k_scan() {
    const int tid = threadIdx.x, lane = tid & 31, wid = tid >> 5;
    __shared__ int wsum[32];
    __shared__ int carry;
    if (tid == 0) carry = 0;
    __syncthreads();
    for (int base = 0; base < N_NODES; base += 4096) {
        int i0 = base + tid * 4;
        int4 v = make_int4(0, 0, 0, 0);
        if (i0 + 3 < N_NODES) v = *(const int4*)&g_deg[i0];
        else {
            if (i0 + 0 < N_NODES) v.x = g_deg[i0 + 0];
            if (i0 + 1 < N_NODES) v.y = g_deg[i0 + 1];
            if (i0 + 2 < N_NODES) v.z = g_deg[i0 + 2];
            if (i0 + 3 < N_NODES) v.w = g_deg[i0 + 3];
        }
        int tsum = v.x + v.y + v.z + v.w;
        int x = tsum;
        #pragma unroll
        for (int o = 1; o < 32; o <<= 1) {
            int y = __shfl_up_sync(0xffffffffu, x, o);
            if (lane >= o) x += y;
        }
        if (lane == 31) wsum[wid] = x;
        __syncthreads();
        if (wid == 0) {
            int s = wsum[lane];
            #pragma unroll
            for (int o = 1; o < 32; o <<= 1) {
                int y = __shfl_up_sync(0xffffffffu, s, o);
                if (lane >= o) s += y;
            }
            wsum[lane] = s;
        }
        __syncthreads();
        int excl = carry + (x - tsum) + (wid ? wsum[wid - 1] : 0);
        if (i0 + 0 < N_NODES) { g_off[i0 + 0] = excl; g_pos[i0 + 0] = 0; } excl += v.x;
        if (i0 + 1 < N_NODES) { g_off[i0 + 1] = excl; g_pos[i0 + 1] = 0; } excl += v.y;
        if (i0 + 2 < N_NODES) { g_off[i0 + 2] = excl; g_pos[i0 + 2] = 0; } excl += v.z;
        if (i0 + 3 < N_NODES) { g_off[i0 + 3] = excl; g_pos[i0 + 3] = 0; }
        int tot = wsum[31];
        __syncthreads();
        if (tid == 0) carry += tot;
        __syncthreads();
    }
    if (tid == 0) g_off[N_NODES] = carry;
}
__global__ void k_fill() {
    int e = blockIdx.x * blockDim.x + threadIdx.x;
    if (e >= N_EDGES) return;
    int d = g_edst[e];
    int p = atomicAdd(&g_pos[d], 1);
    g_eid[g_off[d] + p] = e;
}

// ---------------- A conversion: x float -> g_A1[:, 0:256] half ---------------
__global__ void k_cvtA1(const float* __restrict__ x) {
    long long i = (long long)blockIdx.x * blockDim.x + threadIdx.x;  // half2 units
    if (i >= (long long)N_NODES * 128) return;
    int n  = (int)(i >> 7);
    int c2 = (int)(i & 127);
    float2 v = ((const float2*)x)[(long long)n * 128 + c2];
    *(__half2*)&g_A1[(size_t)n * K1 + c2 * 2] = __floats2half2_rn(v.x, v.y);
}

// ---------------- basis-combined CSR aggregation ----------------
// One block per dst node, Fin/4 threads. Z_b[n] = sum_edges comp[t,b]/cnt * A[src]
// A rows: [features | Z0..Z3] of stride K = 5*Fin; writes cols [Fin, 5Fin).
__global__ void k_aggZ(__half* __restrict__ Abase, const float* __restrict__ comp,
                       int Fin, int K) {
    __shared__ float scomp[N_REL * N_BASES];
    int n = blockIdx.x;
    int tid = threadIdx.x;
    if (tid < N_REL * N_BASES) scomp[tid] = comp[tid];
    __syncthreads();
    int beg = g_off[n], end = g_off[n + 1];
    float z0[4] = {}, z1[4] = {}, z2[4] = {}, z3[4] = {};
    for (int j = beg; j < end; j++) {
        int e = g_eid[j];
        int s = g_esrc[e], t = g_etyp[e];
        float scl = 1.0f / (float)g_cnt[n * N_REL + t];
        float c0 = scomp[t * 4 + 0] * scl, c1 = scomp[t * 4 + 1] * scl;
        float c2 = scomp[t * 4 + 2] * scl, c3 = scomp[t * 4 + 3] * scl;
        const __half2* h = (const __half2*)&Abase[(size_t)s * K + tid * 4];
        float2 f0 = __half22float2(h[0]);
        float2 f1 = __half22float2(h[1]);
        float v[4] = { f0.x, f0.y, f1.x, f1.y };
        #pragma unroll
        for (int i = 0; i < 4; i++) {
            z0[i] = fmaf(v[i], c0, z0[i]);
            z1[i] = fmaf(v[i], c1, z1[i]);
            z2[i] = fmaf(v[i], c2, z2[i]);
            z3[i] = fmaf(v[i], c3, z3[i]);
        }
    }
    __half2* d0 = (__half2*)&Abase[(size_t)n * K + Fin * 1 + tid * 4];
    __half2* d1 = (__half2*)&Abase[(size_t)n * K + Fin * 2 + tid * 4];
    __half2* d2 = (__half2*)&Abase[(size_t)n * K + Fin * 3 + tid * 4];
    __half2* d3 = (__half2*)&Abase[(size_t)n * K + Fin * 4 + tid * 4];
    d0[0] = __floats2half2_rn(z0[0], z0[1]); d0[1] = __floats2half2_rn(z0[2], z0[3]);
    d1[0] = __floats2half2_rn(z1[0], z1[1]); d1[1] = __floats2half2_rn(z1[2], z1[3]);
    d2[0] = __floats2half2_rn(z2[0], z2[1]); d2[1] = __floats2half2_rn(z2[2], z2[3]);
    d3[0] = __floats2half2_rn(z3[0], z3[1]); d3[1] = __floats2half2_rn(z3[2], z3[3]);
}

// ---------------- weight build: g_Wh[j, kidx] (K-major), j<768 ---------------
// kidx < Fin -> root[kidx, j] ; else basis_b[k, j], b=(kidx-Fin)/Fin, k=(kidx-Fin)%Fin
__global__ void k_buildW(const float* __restrict__ root,
                         const float* __restrict__ basis, int Fin, int K) {
    long long i = (long long)blockIdx.x * blockDim.x + threadIdx.x;
    long long tot = (long long)768 * K;
    if (i >= tot) return;
    int j = (int)(i / K), kidx = (int)(i % K);
    float v;
    if (kidx < Fin) {
        v = root[(long long)kidx * 768 + j];
    } else {
        int t = kidx - Fin;
        int b = t / Fin, k = t % Fin;
        v = basis[((long long)b * Fin + k) * 768 + j];
    }
    g_Wh[i] = __float2half_rn(v);
}

// ---------------- pointwise ----------------
// BN(eval) + ReLU; reads g_acc float, writes g_A2[:, 0:768] half
__global__ void k_bnrelu(const float* __restrict__ gamma, const float* __restrict__ beta,
                         const float* __restrict__ mean,  const float* __restrict__ var) {
    long long i = (long long)blockIdx.x * blockDim.x + threadIdx.x;
    if (i >= (long long)N_NODES * 192) return;
    int n = (int)(i / 192);
    int f = (int)(i % 192) * 4;
    float4 v = ((float4*)g_acc)[i];
    float r0 = fmaxf((v.x - mean[f+0]) * rsqrtf(var[f+0] + 1e-5f) * gamma[f+0] + beta[f+0], 0.f);
    float r1 = fmaxf((v.y - mean[f+1]) * rsqrtf(var[f+1] + 1e-5f) * gamma[f+1] + beta[f+1], 0.f);
    float r2 = fmaxf((v.z - mean[f+2]) * rsqrtf(var[f+2] + 1e-5f) * gamma[f+2] + beta[f+2], 0.f);
    float r3 = fmaxf((v.w - mean[f+3]) * rsqrtf(var[f+3] + 1e-5f) * gamma[f+3] + beta[f+3], 0.f);
    __half2* dst = (__half2*)&g_A2[(size_t)n * K2 + f];
    dst[0] = __floats2half2_rn(r0, r1);
    dst[1] = __floats2half2_rn(r2, r3);
}
__global__ void k_l2norm(float* __restrict__ out) {
    int n = blockIdx.x;
    float4 v = *(float4*)&out[(long long)n * 768 + threadIdx.x * 4];
    float ss = v.x*v.x + v.y*v.y + v.z*v.z + v.w*v.w;
    #pragma unroll
    for (int o = 16; o > 0; o >>= 1)
        ss += __shfl_xor_sync(0xffffffffu, ss, o);
    __shared__ float sw[6];
    __shared__ float s_inv;
    int wid = threadIdx.x / 32;
    if ((threadIdx.x & 31) == 0) sw[wid] = ss;
    __syncthreads();
    if (threadIdx.x == 0) {
        float tot = sw[0] + sw[1] + sw[2] + sw[3] + sw[4] + sw[5];
        s_inv = 1.0f / fmaxf(sqrtf(tot), 1e-12f);
    }
    __syncthreads();
    float inv = s_inv;
    v.x *= inv; v.y *= inv; v.z *= inv; v.w *= inv;
    *(float4*)&out[(long long)n * 768 + threadIdx.x * 4] = v;
}

// ---------------- launch ----------------
extern "C" void kernel_launch(void* const* d_in, const int* in_sizes, int n_in,
                              void* d_out, int out_size) {
    const float* x       = (const float*)d_in[0];
    const void*  ei      = d_in[1];
    const void*  et      = d_in[2];
    const float* basis1  = (const float*)d_in[3];
    const float* comp1   = (const float*)d_in[4];
    const float* root1   = (const float*)d_in[5];
    const float* bias1   = (const float*)d_in[6];
    const float* bn_g    = (const float*)d_in[7];
    const float* bn_b    = (const float*)d_in[8];
    const float* bn_m    = (const float*)d_in[9];
    const float* bn_v    = (const float*)d_in[10];
    const float* basis2  = (const float*)d_in[11];
    const float* comp2   = (const float*)d_in[12];
    const float* root2   = (const float*)d_in[13];
    const float* bias2   = (const float*)d_in[14];
    float* out = (float*)d_out;

    float*  g_acc_p; cudaGetSymbolAddress((void**)&g_acc_p, g_acc);
    __half* g_A1_p;  cudaGetSymbolAddress((void**)&g_A1_p,  g_A1);
    __half* g_A2_p;  cudaGetSymbolAddress((void**)&g_A2_p,  g_A2);

    cudaFuncSetAttribute(k_gemm_mma, cudaFuncAttributeMaxDynamicSharedMemorySize, SM_TOTAL);

    const int EB = (N_EDGES + 255) / 256;
    const int PW = (int)(((long long)N_NODES * 192 + 255) / 256);
    dim3 gemm_grid(768 / BN, (N_NODES + BM - 1) / BM);

    // edge preprocessing + CSR build (shared by both layers)
    k_detect<<<1, 256>>>((const int*)ei);
    k_zero<<<(N_NODES * N_REL + 255) / 256, 256>>>();
    k_prep<<<EB, 256>>>(ei, et);
    k_scan<<<1, 1024>>>();
    k_fill<<<EB, 256>>>();

    // ---- layer 1 ----
    k_cvtA1<<<(int)(((long long)N_NODES * 128 + 255) / 256), 256>>>(x);
    k_aggZ<<<N_NODES, IN_CH / 4>>>(g_A1_p, comp1, IN_CH, K1);
    k_buildW<<<(int)(((long long)768 * K1 + 255) / 256), 256>>>(root1, basis1, IN_CH, K1);
    k_gemm_mma<<<gemm_grid, 256, SM_TOTAL>>>(g_A1_p, g_acc_p, bias1, N_NODES, K1);
    k_bnrelu<<<PW, 256>>>(bn_g, bn_b, bn_m, bn_v);

    // ---- layer 2 ----
    k_aggZ<<<N_NODES, HID / 4>>>(g_A2_p, comp2, HID, K2);
    k_buildW<<<(int)(((long long)768 * K2 + 255) / 256), 256>>>(root2, basis2, HID, K2);
    k_gemm_mma<<<gemm_grid, 256, SM_TOTAL>>>(g_A2_p, out, bias2, N_NODES, K2);
    k_l2norm<<<N_NODES, 192>>>(out);
}

// round 8
// speedup vs baseline: 6.1004x; 1.0586x over previous
#include <cuda_runtime.h>
#include <cuda_fp16.h>
#include <cstdint>
#include <math.h>

#define N_NODES 50000
#define N_EDGES 200000
#define IN_CH   256
#define HID     768
#define N_REL   5
#define N_BASES 4
#define K1      (5*IN_CH)   /* 1280: [x | Z0..Z3] layer 1 */
#define K2      (5*HID)     /* 3840: [h | Z0..Z3] layer 2 */

// ---------------- static device scratch (no allocations allowed) -------------
__device__ __half g_A1[(size_t)N_NODES * K1];   // layer-1 GEMM A operand (122 MB)
__device__ __half g_A2[(size_t)N_NODES * K2];   // layer-2 GEMM A operand (366 MB)
__device__ __half g_Wh[(size_t)HID * K2];       // B^T: [768, K] K-major, half
__device__ int    g_cnt[N_NODES * N_REL];
__device__ int    g_deg[N_NODES];
__device__ int    g_off[N_NODES];
__device__ int    g_pos[N_NODES];
__device__ int    g_eid[N_EDGES];
__device__ int    g_esrc[N_EDGES];
__device__ int    g_edst[N_EDGES];
__device__ int    g_etyp[N_EDGES];
__device__ int    g_total;
__device__ int    g_is64;

// ============================ helpers ====================================
__device__ __forceinline__ void cp16(uint32_t dst, const void* src, int sz) {
    asm volatile("cp.async.cg.shared.global [%0], [%1], 16, %2;"
                 :: "r"(dst), "l"(src), "r"(sz));
}
__device__ __forceinline__ uint32_t smem_u32(const void* p) {
    uint32_t a;
    asm("{ .reg .u64 t; cvta.to.shared.u64 t, %1; cvt.u32.u64 %0, t; }"
        : "=r"(a) : "l"(p));
    return a;
}
__device__ __forceinline__ void mma16n8k16(float* d, const uint32_t* a, const uint32_t* b) {
    asm volatile(
        "mma.sync.aligned.m16n8k16.row.col.f32.f16.f16.f32 "
        "{%0,%1,%2,%3}, {%4,%5,%6,%7}, {%8,%9}, {%0,%1,%2,%3};"
        : "+f"(d[0]), "+f"(d[1]), "+f"(d[2]), "+f"(d[3])
        : "r"(a[0]), "r"(a[1]), "r"(a[2]), "r"(a[3]), "r"(b[0]), "r"(b[1]));
}
__device__ __forceinline__ void ldsm4(uint32_t& r0, uint32_t& r1, uint32_t& r2,
                                      uint32_t& r3, uint32_t addr) {
    asm volatile("ldmatrix.sync.aligned.m8n8.x4.shared.b16 {%0,%1,%2,%3}, [%4];"
                 : "=r"(r0), "=r"(r1), "=r"(r2), "=r"(r3) : "r"(addr));
}

// ====================== fp16 mma.sync GEMM (fp32 accum) ======================
// out = A[M, K] @ g_Wh^T + bias   (g_Wh is [768, K] K-major, half)
// epi=0: float out to dst[M,768].  epi=1: BN(eval)+ReLU, half out to
//        out_h[row*K2 + col] (layer-2 A operand feature block).
#define BM 128
#define BN 256
#define BK 32
#define AST 40                              /* padded row stride in halves */
#define SA_BUF (BM * AST)
#define SB_BUF (BN * AST)
#define STAGES 3
#define SM_TOTAL (STAGES * (SA_BUF + SB_BUF) * 2)   /* 92160 bytes */

__global__ void __launch_bounds__(256, 1)
k_gemm_mma(const __half* __restrict__ A, float* __restrict__ dst,
           const float* __restrict__ bias, int M, int K, int epi,
           const float* __restrict__ bn_g, const float* __restrict__ bn_b,
           const float* __restrict__ bn_m, const float* __restrict__ bn_v,
           __half* __restrict__ out_h) {
    extern __shared__ __half sm[];
    const uint32_t sb = smem_u32(sm);
    const uint32_t stb = (SA_BUF + SB_BUF) * 2;

    const int tid  = threadIdx.x;
    const int lane = tid & 31;
    const int warp = tid >> 5;
    const int wm   = (warp & 1) * 64;
    const int wn   = (warp >> 1) * 64;
    const int row0 = blockIdx.y * BM;
    const int col0 = blockIdx.x * BN;
    const int NIT  = K / BK;

    const int g = lane >> 2;
    const int c = lane & 3;

    const uint32_t a_off = (((lane & 15) * AST) + ((lane >> 4) * 8)) * 2;
    const uint32_t b_off = ((((lane & 7) + ((lane >> 4) << 3)) * AST)
                            + (((lane >> 3) & 1) * 8)) * 2;

    float acc[4][8][4];
    #pragma unroll
    for (int i = 0; i < 4; i++)
        #pragma unroll
        for (int j = 0; j < 8; j++) {
            acc[i][j][0] = 0.f; acc[i][j][1] = 0.f;
            acc[i][j][2] = 0.f; acc[i][j][3] = 0.f;
        }

    auto load_buf = [&](int it) {
        const int st = it % STAGES;
        const int k0 = it * BK;
        const uint32_t sA = sb + st * stb;
        const uint32_t sB = sA + SA_BUF * 2;
        #pragma unroll
        for (int i = 0; i < 2; i++) {
            int q = tid + i * 256;
            int r = q >> 2, ch = q & 3;
            int grow = row0 + r;
            const __half* src = A + (long long)(grow < M ? grow : M - 1) * K + k0 + ch * 8;
            cp16(sA + (r * AST + ch * 8) * 2, src, (grow < M) ? 16 : 0);
        }
        #pragma unroll
        for (int i = 0; i < 4; i++) {
            int q = tid + i * 256;
            int r = q >> 2, ch = q & 3;
            const __half* src = g_Wh + (long long)(col0 + r) * K + k0 + ch * 8;
            cp16(sB + (r * AST + ch * 8) * 2, src, 16);
        }
        asm volatile("cp.async.commit_group;" ::: "memory");
    };

    load_buf(0);
    load_buf(1);

    for (int it = 0; it < NIT; it++) {
        if (it + 1 < NIT)
            asm volatile("cp.async.wait_group 1;" ::: "memory");
        else
            asm volatile("cp.async.wait_group 0;" ::: "memory");
        __syncthreads();
        if (it + 2 < NIT) load_buf(it + 2);

        const int st = it % STAGES;
        const uint32_t sA = sb + st * stb;
        const uint32_t sB = sA + SA_BUF * 2;

        #pragma unroll
        for (int ks = 0; ks < 2; ks++) {
            uint32_t af[4][4], bf[8][2];
            #pragma unroll
            for (int mt = 0; mt < 4; mt++)
                ldsm4(af[mt][0], af[mt][1], af[mt][2], af[mt][3],
                      sA + a_off + (uint32_t)((wm + mt * 16) * AST * 2) + ks * 32);
            #pragma unroll
            for (int p = 0; p < 4; p++)
                ldsm4(bf[2*p][0], bf[2*p][1], bf[2*p+1][0], bf[2*p+1][1],
                      sB + b_off + (uint32_t)((wn + p * 16) * AST * 2) + ks * 32);
            #pragma unroll
            for (int mt = 0; mt < 4; mt++)
                #pragma unroll
                for (int nt = 0; nt < 8; nt++)
                    mma16n8k16(acc[mt][nt], af[mt], bf[nt]);
        }
    }

    if (epi == 0) {
        #pragma unroll
        for (int mt = 0; mt < 4; mt++) {
            int r0 = row0 + wm + mt * 16 + g;
            #pragma unroll
            for (int nt = 0; nt < 8; nt++) {
                int cc = col0 + wn + nt * 8 + c * 2;
                float2 b = *(const float2*)&bias[cc];
                if (r0 < M)
                    *(float2*)&dst[(long long)r0 * 768 + cc] =
                        make_float2(acc[mt][nt][0] + b.x, acc[mt][nt][1] + b.y);
                if (r0 + 8 < M)
                    *(float2*)&dst[(long long)(r0 + 8) * 768 + cc] =
                        make_float2(acc[mt][nt][2] + b.x, acc[mt][nt][3] + b.y);
            }
        }
    } else {
        // fused bias + BN(eval) + ReLU, half output to layer-2 A operand
        #pragma unroll
        for (int mt = 0; mt < 4; mt++) {
            int r0 = row0 + wm + mt * 16 + g;
            #pragma unroll
            for (int nt = 0; nt < 8; nt++) {
                int cc = col0 + wn + nt * 8 + c * 2;
                float2 b  = *(const float2*)&bias[cc];
                float2 gm = *(const float2*)&bn_g[cc];
                float2 bt = *(const float2*)&bn_b[cc];
                float2 mn = *(const float2*)&bn_m[cc];
                float2 vr = *(const float2*)&bn_v[cc];
                float s0 = rsqrtf(vr.x + 1e-5f) * gm.x;
                float s1 = rsqrtf(vr.y + 1e-5f) * gm.y;
                float lo0 = fmaxf((acc[mt][nt][0] + b.x - mn.x) * s0 + bt.x, 0.f);
                float lo1 = fmaxf((acc[mt][nt][1] + b.y - mn.y) * s1 + bt.y, 0.f);
                float hi0 = fmaxf((acc[mt][nt][2] + b.x - mn.x) * s0 + bt.x, 0.f);
                float hi1 = fmaxf((acc[mt][nt][3] + b.y - mn.y) * s1 + bt.y, 0.f);
                if (r0 < M)
                    *(__half2*)&out_h[(size_t)r0 * K2 + cc] = __floats2half2_rn(lo0, lo1);
                if (r0 + 8 < M)
                    *(__half2*)&out_h[(size_t)(r0 + 8) * K2 + cc] = __floats2half2_rn(hi0, hi1);
            }
        }
    }
}

// ---------------- index-width detection (int32 vs int64 dump) ----------------
__global__ void k_detect(const int* ei) {
    __shared__ int found;
    if (threadIdx.x == 0) found = 0;
    __syncthreads();
    for (int i = threadIdx.x; i < 2048; i += blockDim.x)
        if (ei[2 * i + 1] != 0) found = 1;
    __syncthreads();
    if (threadIdx.x == 0) g_is64 = (found == 0) ? 1 : 0;
}
__device__ __forceinline__ int idx_at(const void* p, long long i, int is64) {
    return is64 ? (int)((const long long*)p)[i] : ((const int*)p)[i];
}

// ---------------- edge preprocessing / CSR build (scan-free) ----------------
__global__ void k_zero() {
    int i = blockIdx.x * blockDim.x + threadIdx.x;
    if (i < N_NODES * N_REL) g_cnt[i] = 0;
    if (i < N_NODES) g_deg[i] = 0;
    if (i == 0) g_total = 0;
}
__global__ void k_prep(const void* ei, const void* et) {
    int e = blockIdx.x * blockDim.x + threadIdx.x;
    if (e >= N_EDGES) return;
    int is64 = g_is64;
    int s = idx_at(ei, e, is64);
    int d = idx_at(ei, (long long)N_EDGES + e, is64);
    int t = idx_at(et, e, is64);
    g_esrc[e] = s; g_edst[e] = d; g_etyp[e] = t;
    atomicAdd(&g_cnt[d * N_REL + t], 1);
    atomicAdd(&g_deg[d], 1);
}
// disjoint range allocation — order irrelevant, no scan needed
__global__ void k_alloc() {
    int i = blockIdx.x * blockDim.x + threadIdx.x;
    if (i >= N_NODES) return;
    g_off[i] = atomicAdd(&g_total, g_deg[i]);
    g_pos[i] = 0;
}
__global__ void k_fill() {
    int e = blockIdx.x * blockDim.x + threadIdx.x;
    if (e >= N_EDGES) return;
    int d = g_edst[e];
    int p = atomicAdd(&g_pos[d], 1);
    g_eid[g_off[d] + p] = e;
}

// ---------------- A conversion: x float -> g_A1[:, 0:256] half ---------------
__global__ void k_cvtA1(const float* __restrict__ x) {
    long long i = (long long)blockIdx.x * blockDim.x + threadIdx.x;  // half2 units
    if (i >= (long long)N_NODES * 128) return;
    int n  = (int)(i >> 7);
    int c2 = (int)(i & 127);
    float2 v = ((const float2*)x)[(long long)n * 128 + c2];
    *(__half2*)&g_A1[(size_t)n * K1 + c2 * 2] = __floats2half2_rn(v.x, v.y);
}

// ---------------- basis-combined CSR aggregation ----------------
// One block per dst node, Fin/4 threads. Z_b[n] = sum_edges comp[t,b]/cnt * A[src]
__global__ void k_aggZ(__half* __restrict__ Abase, const float* __restrict__ comp,
                       int Fin, int K) {
    __shared__ float scomp[N_REL * N_BASES];
    int n = blockIdx.x;
    int tid = threadIdx.x;
    if (tid < N_REL * N_BASES) scomp[tid] = comp[tid];
    __syncthreads();
    int beg = g_off[n], end = beg + g_deg[n];
    float z0[4] = {}, z1[4] = {}, z2[4] = {}, z3[4] = {};
    for (int j = beg; j < end; j++) {
        int e = g_eid[j];
        int s = g_esrc[e], t = g_etyp[e];
        float scl = 1.0f / (float)g_cnt[n * N_REL + t];
        float c0 = scomp[t * 4 + 0] * scl, c1 = scomp[t * 4 + 1] * scl;
        float c2 = scomp[t * 4 + 2] * scl, c3 = scomp[t * 4 + 3] * scl;
        const __half2* h = (const __half2*)&Abase[(size_t)s * K + tid * 4];
        float2 f0 = __half22float2(h[0]);
        float2 f1 = __half22float2(h[1]);
        float v[4] = { f0.x, f0.y, f1.x, f1.y };
        #pragma unroll
        for (int i = 0; i < 4; i++) {
            z0[i] = fmaf(v[i], c0, z0[i]);
            z1[i] = fmaf(v[i], c1, z1[i]);
            z2[i] = fmaf(v[i], c2, z2[i]);
            z3[i] = fmaf(v[i], c3, z3[i]);
        }
    }
    __half2* d0 = (__half2*)&Abase[(size_t)n * K + Fin * 1 + tid * 4];
    __half2* d1 = (__half2*)&Abase[(size_t)n * K + Fin * 2 + tid * 4];
    __half2* d2 = (__half2*)&Abase[(size_t)n * K + Fin * 3 + tid * 4];
    __half2* d3 = (__half2*)&Abase[(size_t)n * K + Fin * 4 + tid * 4];
    d0[0] = __floats2half2_rn(z0[0], z0[1]); d0[1] = __floats2half2_rn(z0[2], z0[3]);
    d1[0] = __floats2half2_rn(z1[0], z1[1]); d1[1] = __floats2half2_rn(z1[2], z1[3]);
    d2[0] = __floats2half2_rn(z2[0], z2[1]); d2[1] = __floats2half2_rn(z2[2], z2[3]);
    d3[0] = __floats2half2_rn(z3[0], z3[1]); d3[1] = __floats2half2_rn(z3[2], z3[3]);
}

// ---------------- weight build: g_Wh[j, kidx] (K-major), j<768 ---------------
__global__ void k_buildW(const float* __restrict__ root,
                         const float* __restrict__ basis, int Fin, int K) {
    long long i = (long long)blockIdx.x * blockDim.x + threadIdx.x;
    long long tot = (long long)768 * K;
    if (i >= tot) return;
    int j = (int)(i / K), kidx = (int)(i % K);
    float v;
    if (kidx < Fin) {
        v = root[(long long)kidx * 768 + j];
    } else {
        int t = kidx - Fin;
        int b = t / Fin, k = t % Fin;
        v = basis[((long long)b * Fin + k) * 768 + j];
    }
    g_Wh[i] = __float2half_rn(v);
}

// ---------------- L2 normalize ----------------
__global__ void k_l2norm(float* __restrict__ out) {
    int n = blockIdx.x;
    float4 v = *(float4*)&out[(long long)n * 768 + threadIdx.x * 4];
    float ss = v.x*v.x + v.y*v.y + v.z*v.z + v.w*v.w;
    #pragma unroll
    for (int o = 16; o > 0; o >>= 1)
        ss += __shfl_xor_sync(0xffffffffu, ss, o);
    __shared__ float sw[6];
    __shared__ float s_inv;
    int wid = threadIdx.x / 32;
    if ((threadIdx.x & 31) == 0) sw[wid] = ss;
    __syncthreads();
    if (threadIdx.x == 0) {
        float tot = sw[0] + sw[1] + sw[2] + sw[3] + sw[4] + sw[5];
        s_inv = 1.0f / fmaxf(sqrtf(tot), 1e-12f);
    }
    __syncthreads();
    float inv = s_inv;
    v.x *= inv; v.y *= inv; v.z *= inv; v.w *= inv;
    *(float4*)&out[(long long)n * 768 + threadIdx.x * 4] = v;
}

// ---------------- launch ----------------
extern "C" void kernel_launch(void* const* d_in, const int* in_sizes, int n_in,
                              void* d_out, int out_size) {
    const float* x       = (const float*)d_in[0];
    const void*  ei      = d_in[1];
    const void*  et      = d_in[2];
    const float* basis1  = (const float*)d_in[3];
    const float* comp1   = (const float*)d_in[4];
    const float* root1   = (const float*)d_in[5];
    const float* bias1   = (const float*)d_in[6];
    const float* bn_g    = (const float*)d_in[7];
    const float* bn_b    = (const float*)d_in[8];
    const float* bn_m    = (const float*)d_in[9];
    const float* bn_v    = (const float*)d_in[10];
    const float* basis2  = (const float*)d_in[11];
    const float* comp2   = (const float*)d_in[12];
    const float* root2   = (const float*)d_in[13];
    const float* bias2   = (const float*)d_in[14];
    float* out = (float*)d_out;

    __half* g_A1_p;  cudaGetSymbolAddress((void**)&g_A1_p,  g_A1);
    __half* g_A2_p;  cudaGetSymbolAddress((void**)&g_A2_p,  g_A2);

    cudaFuncSetAttribute(k_gemm_mma, cudaFuncAttributeMaxDynamicSharedMemorySize, SM_TOTAL);

    const int EB = (N_EDGES + 255) / 256;
    dim3 gemm_grid(768 / BN, (N_NODES + BM - 1) / BM);

    // edge preprocessing + CSR build (shared by both layers)
    k_detect<<<1, 256>>>((const int*)ei);
    k_zero<<<(N_NODES * N_REL + 255) / 256, 256>>>();
    k_prep<<<EB, 256>>>(ei, et);
    k_alloc<<<(N_NODES + 255) / 256, 256>>>();
    k_fill<<<EB, 256>>>();

    // ---- layer 1 (GEMM epilogue fuses bias + BN + ReLU -> g_A2 features) ----
    k_cvtA1<<<(int)(((long long)N_NODES * 128 + 255) / 256), 256>>>(x);
    k_aggZ<<<N_NODES, IN_CH / 4>>>(g_A1_p, comp1, IN_CH, K1);
    k_buildW<<<(int)(((long long)768 * K1 + 255) / 256), 256>>>(root1, basis1, IN_CH, K1);
    k_gemm_mma<<<gemm_grid, 256, SM_TOTAL>>>(g_A1_p, nullptr, bias1, N_NODES, K1, 1,
                                             bn_g, bn_b, bn_m, bn_v, g_A2_p);

    // ---- layer 2 ----
    k_aggZ<<<N_NODES, HID / 4>>>(g_A2_p, comp2, HID, K2);
    k_buildW<<<(int)(((long long)768 * K2 + 255) / 256), 256>>>(root2, basis2, HID, K2);
    k_gemm_mma<<<gemm_grid, 256, SM_TOTAL>>>(g_A2_p, out, bias2, N_NODES, K2, 0,
                                             nullptr, nullptr, nullptr, nullptr, nullptr);
    k_l2norm<<<N_NODES, 192>>>(out);
}

// round 9
// speedup vs baseline: 6.5753x; 1.0778x over previous
#include <cuda_runtime.h>
#include <cuda_fp16.h>
#include <cstdint>
#include <math.h>

#define N_NODES 50000
#define N_EDGES 200000
#define IN_CH   256
#define HID     768
#define N_REL   5
#define N_BASES 4
#define K1      (5*IN_CH)   /* 1280: [x | Z0..Z3] layer 1 */
#define K2      (5*HID)     /* 3840: [h | Z0..Z3] layer 2 */

// ---------------- static device scratch (no allocations allowed) -------------
__device__ __half g_A1[(size_t)N_NODES * K1];   // layer-1 GEMM A operand (122 MB)
__device__ __half g_A2[(size_t)N_NODES * K2];   // layer-2 GEMM A operand (366 MB)
__device__ __half g_Wh1[(size_t)HID * K1];      // layer-1 B^T (K-major, half)
__device__ __half g_Wh2[(size_t)HID * K2];      // layer-2 B^T (K-major, half)
__device__ int    g_cnt[N_NODES * N_REL];
__device__ int    g_deg[N_NODES];
__device__ int    g_off[N_NODES];
__device__ int    g_pos[N_NODES];
__device__ int2   g_es[N_EDGES];                // per-slot {src|(t<<20), bits(1/cnt)}
__device__ int    g_esrc[N_EDGES];
__device__ int    g_edst[N_EDGES];
__device__ int    g_etyp[N_EDGES];
__device__ int    g_total;
__device__ int    g_is64;

// ============================ helpers ====================================
__device__ __forceinline__ void cp16(uint32_t dst, const void* src, int sz) {
    asm volatile("cp.async.cg.shared.global [%0], [%1], 16, %2;"
                 :: "r"(dst), "l"(src), "r"(sz));
}
__device__ __forceinline__ uint32_t smem_u32(const void* p) {
    uint32_t a;
    asm("{ .reg .u64 t; cvta.to.shared.u64 t, %1; cvt.u32.u64 %0, t; }"
        : "=r"(a) : "l"(p));
    return a;
}
__device__ __forceinline__ void mma16n8k16(float* d, const uint32_t* a, const uint32_t* b) {
    asm volatile(
        "mma.sync.aligned.m16n8k16.row.col.f32.f16.f16.f32 "
        "{%0,%1,%2,%3}, {%4,%5,%6,%7}, {%8,%9}, {%0,%1,%2,%3};"
        : "+f"(d[0]), "+f"(d[1]), "+f"(d[2]), "+f"(d[3])
        : "r"(a[0]), "r"(a[1]), "r"(a[2]), "r"(a[3]), "r"(b[0]), "r"(b[1]));
}
__device__ __forceinline__ void ldsm4(uint32_t& r0, uint32_t& r1, uint32_t& r2,
                                      uint32_t& r3, uint32_t addr) {
    asm volatile("ldmatrix.sync.aligned.m8n8.x4.shared.b16 {%0,%1,%2,%3}, [%4];"
                 : "=r"(r0), "=r"(r1), "=r"(r2), "=r"(r3) : "r"(addr));
}

// ====================== fp16 mma.sync GEMM (fp32 accum) ======================
#define BM 128
#define BN 256
#define BK 32
#define AST 40                              /* padded row stride in halves */
#define SA_BUF (BM * AST)
#define SB_BUF (BN * AST)
#define STAGES 3
#define SM_TOTAL (STAGES * (SA_BUF + SB_BUF) * 2)   /* 92160 bytes */

__global__ void __launch_bounds__(256, 1)
k_gemm_mma(const __half* __restrict__ A, const __half* __restrict__ W,
           float* __restrict__ dst, const float* __restrict__ bias,
           int M, int K, int epi,
           const float* __restrict__ bn_g, const float* __restrict__ bn_b,
           const float* __restrict__ bn_m, const float* __restrict__ bn_v,
           __half* __restrict__ out_h) {
    extern __shared__ __half sm[];
    const uint32_t sb = smem_u32(sm);
    const uint32_t stb = (SA_BUF + SB_BUF) * 2;

    const int tid  = threadIdx.x;
    const int lane = tid & 31;
    const int warp = tid >> 5;
    const int wm   = (warp & 1) * 64;
    const int wn   = (warp >> 1) * 64;
    const int row0 = blockIdx.y * BM;
    const int col0 = blockIdx.x * BN;
    const int NIT  = K / BK;

    const int g = lane >> 2;
    const int c = lane & 3;

    const uint32_t a_off = (((lane & 15) * AST) + ((lane >> 4) * 8)) * 2;
    const uint32_t b_off = ((((lane & 7) + ((lane >> 4) << 3)) * AST)
                            + (((lane >> 3) & 1) * 8)) * 2;

    float acc[4][8][4];
    #pragma unroll
    for (int i = 0; i < 4; i++)
        #pragma unroll
        for (int j = 0; j < 8; j++) {
            acc[i][j][0] = 0.f; acc[i][j][1] = 0.f;
            acc[i][j][2] = 0.f; acc[i][j][3] = 0.f;
        }

    auto load_buf = [&](int it) {
        const int st = it % STAGES;
        const int k0 = it * BK;
        const uint32_t sA = sb + st * stb;
        const uint32_t sB = sA + SA_BUF * 2;
        #pragma unroll
        for (int i = 0; i < 2; i++) {
            int q = tid + i * 256;
            int r = q >> 2, ch = q & 3;
            int grow = row0 + r;
            const __half* src = A + (long long)(grow < M ? grow : M - 1) * K + k0 + ch * 8;
            cp16(sA + (r * AST + ch * 8) * 2, src, (grow < M) ? 16 : 0);
        }
        #pragma unroll
        for (int i = 0; i < 4; i++) {
            int q = tid + i * 256;
            int r = q >> 2, ch = q & 3;
            const __half* src = W + (long long)(col0 + r) * K + k0 + ch * 8;
            cp16(sB + (r * AST + ch * 8) * 2, src, 16);
        }
        asm volatile("cp.async.commit_group;" ::: "memory");
    };

    load_buf(0);
    load_buf(1);

    for (int it = 0; it < NIT; it++) {
        if (it + 1 < NIT)
            asm volatile("cp.async.wait_group 1;" ::: "memory");
        else
            asm volatile("cp.async.wait_group 0;" ::: "memory");
        __syncthreads();
        if (it + 2 < NIT) load_buf(it + 2);

        const int st = it % STAGES;
        const uint32_t sA = sb + st * stb;
        const uint32_t sB = sA + SA_BUF * 2;

        #pragma unroll
        for (int ks = 0; ks < 2; ks++) {
            uint32_t af[4][4], bf[8][2];
            #pragma unroll
            for (int mt = 0; mt < 4; mt++)
                ldsm4(af[mt][0], af[mt][1], af[mt][2], af[mt][3],
                      sA + a_off + (uint32_t)((wm + mt * 16) * AST * 2) + ks * 32);
            #pragma unroll
            for (int p = 0; p < 4; p++)
                ldsm4(bf[2*p][0], bf[2*p][1], bf[2*p+1][0], bf[2*p+1][1],
                      sB + b_off + (uint32_t)((wn + p * 16) * AST * 2) + ks * 32);
            #pragma unroll
            for (int mt = 0; mt < 4; mt++)
                #pragma unroll
                for (int nt = 0; nt < 8; nt++)
                    mma16n8k16(acc[mt][nt], af[mt], bf[nt]);
        }
    }

    if (epi == 0) {
        #pragma unroll
        for (int mt = 0; mt < 4; mt++) {
            int r0 = row0 + wm + mt * 16 + g;
            #pragma unroll
            for (int nt = 0; nt < 8; nt++) {
                int cc = col0 + wn + nt * 8 + c * 2;
                float2 b = *(const float2*)&bias[cc];
                if (r0 < M)
                    *(float2*)&dst[(long long)r0 * 768 + cc] =
                        make_float2(acc[mt][nt][0] + b.x, acc[mt][nt][1] + b.y);
                if (r0 + 8 < M)
                    *(float2*)&dst[(long long)(r0 + 8) * 768 + cc] =
                        make_float2(acc[mt][nt][2] + b.x, acc[mt][nt][3] + b.y);
            }
        }
    } else {
        // fused bias + BN(eval) + ReLU, half output to layer-2 A operand
        #pragma unroll
        for (int mt = 0; mt < 4; mt++) {
            int r0 = row0 + wm + mt * 16 + g;
            #pragma unroll
            for (int nt = 0; nt < 8; nt++) {
                int cc = col0 + wn + nt * 8 + c * 2;
                float2 b  = *(const float2*)&bias[cc];
                float2 gm = *(const float2*)&bn_g[cc];
                float2 bt = *(const float2*)&bn_b[cc];
                float2 mn = *(const float2*)&bn_m[cc];
                float2 vr = *(const float2*)&bn_v[cc];
                float s0 = rsqrtf(vr.x + 1e-5f) * gm.x;
                float s1 = rsqrtf(vr.y + 1e-5f) * gm.y;
                float lo0 = fmaxf((acc[mt][nt][0] + b.x - mn.x) * s0 + bt.x, 0.f);
                float lo1 = fmaxf((acc[mt][nt][1] + b.y - mn.y) * s1 + bt.y, 0.f);
                float hi0 = fmaxf((acc[mt][nt][2] + b.x - mn.x) * s0 + bt.x, 0.f);
                float hi1 = fmaxf((acc[mt][nt][3] + b.y - mn.y) * s1 + bt.y, 0.f);
                if (r0 < M)
                    *(__half2*)&out_h[(size_t)r0 * K2 + cc] = __floats2half2_rn(lo0, lo1);
                if (r0 + 8 < M)
                    *(__half2*)&out_h[(size_t)(r0 + 8) * K2 + cc] = __floats2half2_rn(hi0, hi1);
            }
        }
    }
}

// ---------------- index-width detection (int32 vs int64 dump) ----------------
__global__ void k_detect(const int* ei) {
    __shared__ int found;
    if (threadIdx.x == 0) found = 0;
    __syncthreads();
    for (int i = threadIdx.x; i < 2048; i += blockDim.x)
        if (ei[2 * i + 1] != 0) found = 1;
    __syncthreads();
    if (threadIdx.x == 0) g_is64 = (found == 0) ? 1 : 0;
}
__device__ __forceinline__ int idx_at(const void* p, long long i, int is64) {
    return is64 ? (int)((const long long*)p)[i] : ((const int*)p)[i];
}

// ---------------- edge preprocessing / CSR build (scan-free) ----------------
__global__ void k_zero() {
    int i = blockIdx.x * blockDim.x + threadIdx.x;
    if (i < N_NODES * N_REL) g_cnt[i] = 0;
    if (i < N_NODES) g_deg[i] = 0;
    if (i == 0) g_total = 0;
}
__global__ void k_prep(const void* ei, const void* et) {
    int e = blockIdx.x * blockDim.x + threadIdx.x;
    if (e >= N_EDGES) return;
    int is64 = g_is64;
    int s = idx_at(ei, e, is64);
    int d = idx_at(ei, (long long)N_EDGES + e, is64);
    int t = idx_at(et, e, is64);
    g_esrc[e] = s; g_edst[e] = d; g_etyp[e] = t;
    atomicAdd(&g_cnt[d * N_REL + t], 1);
    atomicAdd(&g_deg[d], 1);
}
// disjoint range allocation — order irrelevant, no scan needed
__global__ void k_alloc() {
    int i = blockIdx.x * blockDim.x + threadIdx.x;
    if (i >= N_NODES) return;
    g_off[i] = atomicAdd(&g_total, g_deg[i]);
    g_pos[i] = 0;
}
// fill CSR with pre-packed per-slot metadata {src|(t<<20), bits(1/cnt[d,t])}
__global__ void k_fill() {
    int e = blockIdx.x * blockDim.x + threadIdx.x;
    if (e >= N_EDGES) return;
    int d = g_edst[e];
    int t = g_etyp[e];
    int p = atomicAdd(&g_pos[d], 1);
    float scl = 1.0f / (float)g_cnt[d * N_REL + t];
    g_es[g_off[d] + p] = make_int2(g_esrc[e] | (t << 20), __float_as_int(scl));
}

// ---------------- A conversion: x float -> g_A1[:, 0:256] half ---------------
__global__ void k_cvtA1(const float* __restrict__ x) {
    long long i = (long long)blockIdx.x * blockDim.x + threadIdx.x;  // half2 units
    if (i >= (long long)N_NODES * 128) return;
    int n  = (int)(i >> 7);
    int c2 = (int)(i & 127);
    float2 v = ((const float2*)x)[(long long)n * 128 + c2];
    *(__half2*)&g_A1[(size_t)n * K1 + c2 * 2] = __floats2half2_rn(v.x, v.y);
}

// ---------------- basis-combined CSR aggregation (unroll-2, MLP=2) -----------
// One block per dst node, Fin/4 threads. Z_b[n] = sum_edges comp[t,b]/cnt * A[src]
__global__ void k_aggZ(__half* __restrict__ Abase, const float* __restrict__ comp,
                       int Fin, int K) {
    __shared__ float scomp[N_REL * N_BASES];
    int n = blockIdx.x;
    int tid = threadIdx.x;
    if (tid < N_REL * N_BASES) scomp[tid] = comp[tid];
    __syncthreads();
    int beg = g_off[n], deg = g_deg[n];
    float z0[4] = {}, z1[4] = {}, z2[4] = {}, z3[4] = {};
    int j = 0;
    for (; j + 2 <= deg; j += 2) {
        int2 m0 = g_es[beg + j];
        int2 m1 = g_es[beg + j + 1];
        int sA = m0.x & 0xFFFFF, tA = m0.x >> 20;
        int sB = m1.x & 0xFFFFF, tB = m1.x >> 20;
        const __half2* hA = (const __half2*)&Abase[(size_t)sA * K + tid * 4];
        const __half2* hB = (const __half2*)&Abase[(size_t)sB * K + tid * 4];
        float2 a0 = __half22float2(hA[0]);
        float2 a1 = __half22float2(hA[1]);
        float2 b0 = __half22float2(hB[0]);
        float2 b1 = __half22float2(hB[1]);
        float fA = __int_as_float(m0.y), fB = __int_as_float(m1.y);
        float cA0 = scomp[tA*4+0]*fA, cA1 = scomp[tA*4+1]*fA;
        float cA2 = scomp[tA*4+2]*fA, cA3 = scomp[tA*4+3]*fA;
        float cB0 = scomp[tB*4+0]*fB, cB1 = scomp[tB*4+1]*fB;
        float cB2 = scomp[tB*4+2]*fB, cB3 = scomp[tB*4+3]*fB;
        float vA[4] = { a0.x, a0.y, a1.x, a1.y };
        float vB[4] = { b0.x, b0.y, b1.x, b1.y };
        #pragma unroll
        for (int i = 0; i < 4; i++) {
            z0[i] = fmaf(vA[i], cA0, fmaf(vB[i], cB0, z0[i]));
            z1[i] = fmaf(vA[i], cA1, fmaf(vB[i], cB1, z1[i]));
            z2[i] = fmaf(vA[i], cA2, fmaf(vB[i], cB2, z2[i]));
            z3[i] = fmaf(vA[i], cA3, fmaf(vB[i], cB3, z3[i]));
        }
    }
    if (j < deg) {
        int2 m0 = g_es[beg + j];
        int sA = m0.x & 0xFFFFF, tA = m0.x >> 20;
        const __half2* hA = (const __half2*)&Abase[(size_t)sA * K + tid * 4];
        float2 a0 = __half22float2(hA[0]);
        float2 a1 = __half22float2(hA[1]);
        float fA = __int_as_float(m0.y);
        float cA0 = scomp[tA*4+0]*fA, cA1 = scomp[tA*4+1]*fA;
        float cA2 = scomp[tA*4+2]*fA, cA3 = scomp[tA*4+3]*fA;
        float vA[4] = { a0.x, a0.y, a1.x, a1.y };
        #pragma unroll
        for (int i = 0; i < 4; i++) {
            z0[i] = fmaf(vA[i], cA0, z0[i]);
            z1[i] = fmaf(vA[i], cA1, z1[i]);
            z2[i] = fmaf(vA[i], cA2, z2[i]);
            z3[i] = fmaf(vA[i], cA3, z3[i]);
        }
    }
    __half2* d0 = (__half2*)&Abase[(size_t)n * K + Fin * 1 + tid * 4];
    __half2* d1 = (__half2*)&Abase[(size_t)n * K + Fin * 2 + tid * 4];
    __half2* d2 = (__half2*)&Abase[(size_t)n * K + Fin * 3 + tid * 4];
    __half2* d3 = (__half2*)&Abase[(size_t)n * K + Fin * 4 + tid * 4];
    d0[0] = __floats2half2_rn(z0[0], z0[1]); d0[1] = __floats2half2_rn(z0[2], z0[3]);
    d1[0] = __floats2half2_rn(z1[0], z1[1]); d1[1] = __floats2half2_rn(z1[2], z1[3]);
    d2[0] = __floats2half2_rn(z2[0], z2[1]); d2[1] = __floats2half2_rn(z2[2], z2[3]);
    d3[0] = __floats2half2_rn(z3[0], z3[1]); d3[1] = __floats2half2_rn(z3[2], z3[3]);
}

// ---------------- weight build: W[j, kidx] (K-major), j<768 ------------------
__global__ void k_buildW(const float* __restrict__ root,
                         const float* __restrict__ basis, int Fin, int K,
                         __half* __restrict__ W) {
    long long i = (long long)blockIdx.x * blockDim.x + threadIdx.x;
    long long tot = (long long)768 * K;
    if (i >= tot) return;
    int j = (int)(i / K), kidx = (int)(i % K);
    float v;
    if (kidx < Fin) {
        v = root[(long long)kidx * 768 + j];
    } else {
        int t = kidx - Fin;
        int b = t / Fin, k = t % Fin;
        v = basis[((long long)b * Fin + k) * 768 + j];
    }
    W[i] = __float2half_rn(v);
}

// ---------------- L2 normalize ----------------
__global__ void k_l2norm(float* __restrict__ out) {
    int n = blockIdx.x;
    float4 v = *(float4*)&out[(long long)n * 768 + threadIdx.x * 4];
    float ss = v.x*v.x + v.y*v.y + v.z*v.z + v.w*v.w;
    #pragma unroll
    for (int o = 16; o > 0; o >>= 1)
        ss += __shfl_xor_sync(0xffffffffu, ss, o);
    __shared__ float sw[6];
    __shared__ float s_inv;
    int wid = threadIdx.x / 32;
    if ((threadIdx.x & 31) == 0) sw[wid] = ss;
    __syncthreads();
    if (threadIdx.x == 0) {
        float tot = sw[0] + sw[1] + sw[2] + sw[3] + sw[4] + sw[5];
        s_inv = 1.0f / fmaxf(sqrtf(tot), 1e-12f);
    }
    __syncthreads();
    float inv = s_inv;
    v.x *= inv; v.y *= inv; v.z *= inv; v.w *= inv;
    *(float4*)&out[(long long)n * 768 + threadIdx.x * 4] = v;
}

// ---------------- launch ----------------
extern "C" void kernel_launch(void* const* d_in, const int* in_sizes, int n_in,
                              void* d_out, int out_size) {
    const float* x       = (const float*)d_in[0];
    const void*  ei      = d_in[1];
    const void*  et      = d_in[2];
    const float* basis1  = (const float*)d_in[3];
    const float* comp1   = (const float*)d_in[4];
    const float* root1   = (const float*)d_in[5];
    const float* bias1   = (const float*)d_in[6];
    const float* bn_g    = (const float*)d_in[7];
    const float* bn_b    = (const float*)d_in[8];
    const float* bn_m    = (const float*)d_in[9];
    const float* bn_v    = (const float*)d_in[10];
    const float* basis2  = (const float*)d_in[11];
    const float* comp2   = (const float*)d_in[12];
    const float* root2   = (const float*)d_in[13];
    const float* bias2   = (const float*)d_in[14];
    float* out = (float*)d_out;

    __half* g_A1_p;  cudaGetSymbolAddress((void**)&g_A1_p,  g_A1);
    __half* g_A2_p;  cudaGetSymbolAddress((void**)&g_A2_p,  g_A2);
    __half* g_W1_p;  cudaGetSymbolAddress((void**)&g_W1_p,  g_Wh1);
    __half* g_W2_p;  cudaGetSymbolAddress((void**)&g_W2_p,  g_Wh2);

    cudaFuncSetAttribute(k_gemm_mma, cudaFuncAttributeMaxDynamicSharedMemorySize, SM_TOTAL);

    const int EB = (N_EDGES + 255) / 256;
    dim3 gemm_grid(768 / BN, (N_NODES + BM - 1) / BM);

    // fork a side stream for param-only kernels (captures as graph branches)
    cudaStream_t s1;
    cudaEvent_t evF, evJ;
    cudaStreamCreateWithFlags(&s1, cudaStreamNonBlocking);
    cudaEventCreateWithFlags(&evF, cudaEventDisableTiming);
    cudaEventCreateWithFlags(&evJ, cudaEventDisableTiming);

    k_detect<<<1, 256>>>((const int*)ei);
    cudaEventRecord(evF, 0);
    cudaStreamWaitEvent(s1, evF, 0);

    // branch s1: independent of edge data
    k_buildW<<<(int)(((long long)768 * K1 + 255) / 256), 256, 0, s1>>>(root1, basis1, IN_CH, K1, g_W1_p);
    k_buildW<<<(int)(((long long)768 * K2 + 255) / 256), 256, 0, s1>>>(root2, basis2, HID, K2, g_W2_p);
    k_cvtA1<<<(int)(((long long)N_NODES * 128 + 255) / 256), 256, 0, s1>>>(x);

    // branch 0: edge preprocessing + CSR build
    k_zero<<<(N_NODES * N_REL + 255) / 256, 256>>>();
    k_prep<<<EB, 256>>>(ei, et);
    k_alloc<<<(N_NODES + 255) / 256, 256>>>();
    k_fill<<<EB, 256>>>();

    cudaEventRecord(evJ, s1);
    cudaStreamWaitEvent(0, evJ, 0);

    // ---- layer 1 (GEMM epilogue fuses bias + BN + ReLU -> g_A2 features) ----
    k_aggZ<<<N_NODES, IN_CH / 4>>>(g_A1_p, comp1, IN_CH, K1);
    k_gemm_mma<<<gemm_grid, 256, SM_TOTAL>>>(g_A1_p, g_W1_p, nullptr, bias1, N_NODES, K1, 1,
                                             bn_g, bn_b, bn_m, bn_v, g_A2_p);

    // ---- layer 2 ----
    k_aggZ<<<N_NODES, HID / 4>>>(g_A2_p, comp2, HID, K2);
    k_gemm_mma<<<gemm_grid, 256, SM_TOTAL>>>(g_A2_p, g_W2_p, out, bias2, N_NODES, K2, 0,
                                             nullptr, nullptr, nullptr, nullptr, nullptr);
    k_l2norm<<<N_NODES, 192>>>(out);

    cudaStreamDestroy(s1);
    cudaEventDestroy(evF);
    cudaEventDestroy(evJ);
}